// round 2
// baseline (speedup 1.0000x reference)
#include <cuda_runtime.h>
#include <math.h>

// ---------------- problem constants ----------------
#define N_NODES   131072
#define G_GRAPHS  1024
#define NPG0      128
#define H_DIM     128
#define E_EDGES   2097152
#define EPG       2048          // edges per graph
#define L_LAYERS  3
#define C_CLASSES 10
#define BN_EPS    1e-5f
#define INV_SQRT2 0.70710678118654752440f

// ---------------- scratch (static device memory; no allocs) ----------------
__device__ float g_bufA[(size_t)N_NODES * H_DIM];          // 64 MB
__device__ float g_bufB[(size_t)N_NODES * H_DIM];          // 64 MB
__device__ float g_X[(size_t)(N_NODES / 2) * H_DIM];       // 32 MB (pooled x, reused)
__device__ float g_embraw[G_GRAPHS * H_DIM];
__device__ float g_embcat[G_GRAPHS * L_LAYERS * H_DIM];
__device__ float g_stats[2 * H_DIM];                       // [sum, sumsq]
__device__ float g_scale[H_DIM];
__device__ float g_shift[H_DIM];

#define GEMM_SMEM (2 * 128 * 128 * 4)   // As + Ws = 128 KB

// ---------------- zero stats ----------------
__global__ void zero_stats_kernel(float* stats) {
    stats[threadIdx.x] = 0.f;   // 256 threads
}

// ---------------- GEMM: C[n x 128] = op(A) @ W + bias, + channel stats ----------
// op(A) = A (mode 0) or relu(A*scale + shift) (mode 1)
__global__ __launch_bounds__(256) void gemm128(
    const float* __restrict__ A, const float* __restrict__ W,
    const float* __restrict__ bias,
    const float* __restrict__ scale, const float* __restrict__ shift, int mode,
    float* __restrict__ C, float* __restrict__ stats)
{
    extern __shared__ float sm[];
    float* As = sm;              // 128*128
    float* Ws = sm + 128 * 128;  // 128*128
    const int tid = threadIdx.x;
    const size_t rowbase = (size_t)blockIdx.x * 128;

    const float4* A4 = (const float4*)(A + rowbase * 128);
    const float4* W4 = (const float4*)W;

    #pragma unroll
    for (int it = 0; it < 16; it++) {
        int i = tid + it * 256;
        ((float4*)Ws)[i] = W4[i];
    }
    if (mode) {
        #pragma unroll
        for (int it = 0; it < 16; it++) {
            int i = tid + it * 256;
            float4 v = A4[i];
            int c = (i & 31) * 4;
            v.x = fmaxf(fmaf(v.x, scale[c + 0], shift[c + 0]), 0.f);
            v.y = fmaxf(fmaf(v.y, scale[c + 1], shift[c + 1]), 0.f);
            v.z = fmaxf(fmaf(v.z, scale[c + 2], shift[c + 2]), 0.f);
            v.w = fmaxf(fmaf(v.w, scale[c + 3], shift[c + 3]), 0.f);
            ((float4*)As)[i] = v;
        }
    } else {
        #pragma unroll
        for (int it = 0; it < 16; it++) {
            int i = tid + it * 256;
            ((float4*)As)[i] = A4[i];
        }
    }
    __syncthreads();

    const int tx = tid & 15, ty = tid >> 4;
    const int r0 = ty * 8, c0 = tx * 8;

    float acc[8][8];
    #pragma unroll
    for (int i = 0; i < 8; i++)
        #pragma unroll
        for (int j = 0; j < 8; j++) acc[i][j] = 0.f;

    const float* Asr = As + r0 * 128;
    const float* Wsc = Ws + c0;

    #pragma unroll 4
    for (int k = 0; k < 128; k++) {
        float a[8];
        #pragma unroll
        for (int i = 0; i < 8; i++) a[i] = Asr[i * 128 + k];
        float4 b0 = *(const float4*)(Wsc + k * 128);
        float4 b1 = *(const float4*)(Wsc + k * 128 + 4);
        float b[8] = {b0.x, b0.y, b0.z, b0.w, b1.x, b1.y, b1.z, b1.w};
        #pragma unroll
        for (int i = 0; i < 8; i++)
            #pragma unroll
            for (int j = 0; j < 8; j++)
                acc[i][j] = fmaf(a[i], b[j], acc[i][j]);
    }
    __syncthreads();   // done reading As/Ws; reuse As for stats scratch

    float* csum = As;         // [128]
    float* csq  = As + 128;   // [128]
    if (tid < 64) ((float4*)csum)[tid] = make_float4(0.f, 0.f, 0.f, 0.f);
    __syncthreads();

    float bv[8];
    #pragma unroll
    for (int j = 0; j < 8; j++) bv[j] = __ldg(&bias[c0 + j]);

    float s[8], q[8];
    #pragma unroll
    for (int j = 0; j < 8; j++) { s[j] = 0.f; q[j] = 0.f; }

    float4* C4 = (float4*)(C + rowbase * 128);
    #pragma unroll
    for (int i = 0; i < 8; i++) {
        float y[8];
        #pragma unroll
        for (int j = 0; j < 8; j++) {
            y[j] = acc[i][j] + bv[j];
            s[j] += y[j];
            q[j] += y[j] * y[j];
        }
        float4 o0 = make_float4(y[0], y[1], y[2], y[3]);
        float4 o1 = make_float4(y[4], y[5], y[6], y[7]);
        C4[(r0 + i) * 32 + tx * 2]     = o0;
        C4[(r0 + i) * 32 + tx * 2 + 1] = o1;
    }
    #pragma unroll
    for (int j = 0; j < 8; j++) {
        atomicAdd(&csum[c0 + j], s[j]);
        atomicAdd(&csq[c0 + j],  q[j]);
    }
    __syncthreads();
    if (tid < 128) {
        atomicAdd(&stats[tid],       csum[tid]);
        atomicAdd(&stats[128 + tid], csq[tid]);
    }
}

// ---------------- BN finalize: stats -> (scale, shift), then clear stats -------
__global__ void finalize_kernel(
    const float* __restrict__ gw, const float* __restrict__ bw, float n,
    float* __restrict__ scale, float* __restrict__ shift, float* __restrict__ stats)
{
    int c = threadIdx.x;  // 128
    float s = stats[c], q = stats[128 + c];
    float m = s / n;
    float v = q / n - m * m;
    float sc = gw[c] * rsqrtf(v + BN_EPS);
    scale[c] = sc;
    shift[c] = fmaf(-m, sc, bw[c]);
    stats[c] = 0.f;
    stats[128 + c] = 0.f;
}

// ---------------- GIN aggregation (block per graph, CSR in smem) ---------------
// Hout[d] = x[d] + sum_{e: dst_e==d} x[src_e], with optional BN+relu on x load.
__global__ __launch_bounds__(256) void agg_kernel(
    const float* __restrict__ X, const int* __restrict__ src, const int* __restrict__ dst,
    const float* __restrict__ scale, const float* __restrict__ shift, int mode,
    float* __restrict__ Hout, int npg, int shiftbits)
{
    extern __shared__ float sm[];
    float* xs  = sm;                                   // npg*128 floats
    int*   cnt = (int*)(sm + npg * 128);               // npg+1
    int*   cur = cnt + npg + 1;                        // npg
    int*   ssrc = cur + npg;                           // EPG

    const int g = blockIdx.x, tid = threadIdx.x;
    const float4* X4 = (const float4*)(X + (size_t)g * npg * 128);
    const int nv = npg * 32;

    if (mode) {
        for (int i = tid; i < nv; i += 256) {
            float4 v = X4[i];
            int c = (i & 31) * 4;
            v.x = fmaxf(fmaf(v.x, scale[c + 0], shift[c + 0]), 0.f);
            v.y = fmaxf(fmaf(v.y, scale[c + 1], shift[c + 1]), 0.f);
            v.z = fmaxf(fmaf(v.z, scale[c + 2], shift[c + 2]), 0.f);
            v.w = fmaxf(fmaf(v.w, scale[c + 3], shift[c + 3]), 0.f);
            ((float4*)xs)[i] = v;
        }
    } else {
        for (int i = tid; i < nv; i += 256) ((float4*)xs)[i] = X4[i];
    }
    for (int i = tid; i <= npg; i += 256) cnt[i] = 0;
    __syncthreads();

    const int ebase = g * EPG, nb = g * NPG0;
    for (int e = tid; e < EPG; e += 256) {
        int d = (dst[ebase + e] - nb) >> shiftbits;
        atomicAdd(&cnt[d], 1);
    }
    __syncthreads();
    if (tid == 0) {
        int run = 0;
        for (int d = 0; d < npg; d++) { int t = cnt[d]; cnt[d] = run; run += t; }
        cnt[npg] = run;
    }
    __syncthreads();
    for (int i = tid; i < npg; i += 256) cur[i] = cnt[i];
    __syncthreads();
    for (int e = tid; e < EPG; e += 256) {
        int d = (dst[ebase + e] - nb) >> shiftbits;
        int sl = (src[ebase + e] - nb) >> shiftbits;
        int p = atomicAdd(&cur[d], 1);
        ssrc[p] = sl;
    }
    __syncthreads();

    const int warp = tid >> 5, lane = tid & 31;
    const float4* xs4 = (const float4*)xs;
    float4* H4 = (float4*)(Hout + (size_t)g * npg * 128);
    for (int d = warp; d < npg; d += 8) {
        float4 a = xs4[d * 32 + lane];
        int e0 = cnt[d], e1 = cnt[d + 1];
        for (int p = e0; p < e1; p++) {
            int sl = ssrc[p];
            float4 v = xs4[sl * 32 + lane];
            a.x += v.x; a.y += v.y; a.z += v.z; a.w += v.w;
        }
        H4[d * 32 + lane] = a;
    }
}

// ---------------- BN+relu -> Haar pool -> graph sum (+ embd BN stats) ----------
__global__ __launch_bounds__(256) void pool_kernel(
    const float* __restrict__ Hin, const float* __restrict__ sc, const float* __restrict__ sh,
    float* __restrict__ Xout, float* __restrict__ embraw, float* __restrict__ stats,
    int npg_in)
{
    __shared__ float es[128];
    const int g = blockIdx.x, tid = threadIdx.x;
    if (tid < 128) es[tid] = 0.f;
    __syncthreads();

    const int npg_out = npg_in >> 1;
    const float4* in4 = (const float4*)(Hin + (size_t)g * npg_in * 128);
    float4* out4 = (float4*)(Xout + (size_t)g * npg_out * 128);

    for (int i = tid; i < npg_out * 32; i += 256) {
        int row = i >> 5, c4 = i & 31;
        int c = c4 * 4;
        float4 a = in4[(2 * row) * 32 + c4];
        float4 b = in4[(2 * row + 1) * 32 + c4];
        float4 p;
        p.x = (fmaxf(fmaf(a.x, sc[c+0], sh[c+0]), 0.f) + fmaxf(fmaf(b.x, sc[c+0], sh[c+0]), 0.f)) * INV_SQRT2;
        p.y = (fmaxf(fmaf(a.y, sc[c+1], sh[c+1]), 0.f) + fmaxf(fmaf(b.y, sc[c+1], sh[c+1]), 0.f)) * INV_SQRT2;
        p.z = (fmaxf(fmaf(a.z, sc[c+2], sh[c+2]), 0.f) + fmaxf(fmaf(b.z, sc[c+2], sh[c+2]), 0.f)) * INV_SQRT2;
        p.w = (fmaxf(fmaf(a.w, sc[c+3], sh[c+3]), 0.f) + fmaxf(fmaf(b.w, sc[c+3], sh[c+3]), 0.f)) * INV_SQRT2;
        out4[i] = p;
        atomicAdd(&es[c + 0], p.x);
        atomicAdd(&es[c + 1], p.y);
        atomicAdd(&es[c + 2], p.z);
        atomicAdd(&es[c + 3], p.w);
    }
    __syncthreads();
    if (tid < 128) {
        float v = es[tid];
        embraw[g * 128 + tid] = v;
        atomicAdd(&stats[tid], v);
        atomicAdd(&stats[128 + tid], v * v);
    }
}

// ---------------- embedding BN apply -> concat buffer --------------------------
__global__ void eapply_kernel(
    const float* __restrict__ raw, const float* __restrict__ sc, const float* __restrict__ sh,
    float* __restrict__ cat, int layer)
{
    int idx = blockIdx.x * blockDim.x + threadIdx.x;
    if (idx < G_GRAPHS * H_DIM) {
        int g = idx >> 7, c = idx & 127;
        float v = fmaxf(fmaf(raw[idx], sc[c], sh[c]), 0.f);
        cat[g * (L_LAYERS * H_DIM) + layer * H_DIM + c] = v;
    }
}

// ---------------- final linear [G,384]@[384,10] --------------------------------
__global__ void final_linear_kernel(
    const float* __restrict__ emb, const float* __restrict__ W,
    const float* __restrict__ b, float* __restrict__ out)
{
    const int g = blockIdx.x, lane = threadIdx.x; // 32 threads
    float acc[C_CLASSES];
    #pragma unroll
    for (int c = 0; c < C_CLASSES; c++) acc[c] = 0.f;
    for (int k = lane; k < L_LAYERS * H_DIM; k += 32) {
        float e = emb[g * (L_LAYERS * H_DIM) + k];
        #pragma unroll
        for (int c = 0; c < C_CLASSES; c++)
            acc[c] = fmaf(e, W[k * C_CLASSES + c], acc[c]);
    }
    #pragma unroll
    for (int off = 16; off > 0; off >>= 1)
        #pragma unroll
        for (int c = 0; c < C_CLASSES; c++)
            acc[c] += __shfl_down_sync(0xFFFFFFFFu, acc[c], off);
    if (lane == 0) {
        #pragma unroll
        for (int c = 0; c < C_CLASSES; c++)
            out[g * C_CLASSES + c] = acc[c] + b[c];
    }
}

// ---------------- host orchestration ----------------
extern "C" void kernel_launch(void* const* d_in, const int* in_sizes, int n_in,
                              void* d_out, int out_size)
{
    const float* x            = (const float*)d_in[0];
    const int*   ei           = (const int*)d_in[1];
    const int*   src          = ei;
    const int*   dst          = ei + E_EDGES;
    const float* lin_start_w  = (const float*)d_in[2];
    const float* lin_start_b  = (const float*)d_in[3];
    const float* bn_start_g   = (const float*)d_in[4];
    const float* bn_start_b   = (const float*)d_in[5];
    const float* conv_w1      = (const float*)d_in[6];
    const float* conv_b1      = (const float*)d_in[7];
    const float* conv_bn_g    = (const float*)d_in[8];
    const float* conv_bn_b    = (const float*)d_in[9];
    const float* conv_w2      = (const float*)d_in[10];
    const float* conv_b2      = (const float*)d_in[11];
    const float* bn_g         = (const float*)d_in[12];
    const float* bn_b         = (const float*)d_in[13];
    const float* bne_g        = (const float*)d_in[14];
    const float* bne_b        = (const float*)d_in[15];
    const float* lin_w        = (const float*)d_in[16];
    const float* lin_b        = (const float*)d_in[17];
    float* out = (float*)d_out;

    float *bufA, *bufB, *bufX, *embraw, *embcat, *stats, *scale, *shift;
    cudaGetSymbolAddress((void**)&bufA,   g_bufA);
    cudaGetSymbolAddress((void**)&bufB,   g_bufB);
    cudaGetSymbolAddress((void**)&bufX,   g_X);
    cudaGetSymbolAddress((void**)&embraw, g_embraw);
    cudaGetSymbolAddress((void**)&embcat, g_embcat);
    cudaGetSymbolAddress((void**)&stats,  g_stats);
    cudaGetSymbolAddress((void**)&scale,  g_scale);
    cudaGetSymbolAddress((void**)&shift,  g_shift);

    cudaFuncSetAttribute(gemm128, cudaFuncAttributeMaxDynamicSharedMemorySize, GEMM_SMEM);
    // worst-case agg smem: npg=128
    const int agg_smem0 = NPG0 * 128 * 4 + (2 * NPG0 + 1) * 4 + EPG * 4;
    cudaFuncSetAttribute(agg_kernel, cudaFuncAttributeMaxDynamicSharedMemorySize, agg_smem0);

    zero_stats_kernel<<<1, 256>>>(stats);

    // Stage 0: Y0 = x @ W_start + b  (stats fused)
    gemm128<<<N_NODES / 128, 256, GEMM_SMEM>>>(
        x, lin_start_w, lin_start_b, nullptr, nullptr, 0, bufA, stats);
    finalize_kernel<<<1, 128>>>(bn_start_g, bn_start_b, (float)N_NODES, scale, shift, stats);

    for (int i = 0; i < L_LAYERS; i++) {
        const int n   = N_NODES >> i;
        const int npg = NPG0 >> i;
        const int agg_smem = npg * 128 * 4 + (2 * npg + 1) * 4 + EPG * 4;

        // h = x + sum_neighbors(x); layer 0 fuses bn_start+relu into the x load
        const float* ain = (i == 0) ? (const float*)bufA : (const float*)bufX;
        agg_kernel<<<G_GRAPHS, 256, agg_smem>>>(
            ain, src, dst, scale, shift, (i == 0) ? 1 : 0, bufB, npg, i);

        // h @ W1 + b1 (stats fused)
        gemm128<<<n / 128, 256, GEMM_SMEM>>>(
            bufB, conv_w1 + (size_t)i * H_DIM * H_DIM, conv_b1 + i * H_DIM,
            nullptr, nullptr, 0, bufA, stats);
        finalize_kernel<<<1, 128>>>(conv_bn_g + i * H_DIM, conv_bn_b + i * H_DIM,
                                    (float)n, scale, shift, stats);

        // relu(bn(H1)) @ W2 + b2 (bn+relu fused into A load; stats fused)
        gemm128<<<n / 128, 256, GEMM_SMEM>>>(
            bufA, conv_w2 + (size_t)i * H_DIM * H_DIM, conv_b2 + i * H_DIM,
            scale, shift, 1, bufB, stats);
        finalize_kernel<<<1, 128>>>(bn_g + i * H_DIM, bn_b + i * H_DIM,
                                    (float)n, scale, shift, stats);

        // relu(bn(H2)) -> Haar pool -> x_{i+1}; embd row + embd-BN stats fused
        pool_kernel<<<G_GRAPHS, 256>>>(bufB, scale, shift, bufX, embraw, stats, npg);
        finalize_kernel<<<1, 128>>>(bne_g + i * H_DIM, bne_b + i * H_DIM,
                                    (float)G_GRAPHS, scale, shift, stats);
        eapply_kernel<<<(G_GRAPHS * H_DIM + 255) / 256, 256>>>(embraw, scale, shift, embcat, i);
    }

    final_linear_kernel<<<G_GRAPHS, 32>>>(embcat, lin_w, lin_b, out);
}

// round 4
// speedup vs baseline: 1.1348x; 1.1348x over previous
#include <cuda_runtime.h>
#include <cuda_bf16.h>
#include <math.h>
#include <stdint.h>

// ---------------- problem constants ----------------
#define N_NODES   131072
#define G_GRAPHS  1024
#define NPG0      128
#define H_DIM     128
#define E_EDGES   2097152
#define EPG       2048
#define L_LAYERS  3
#define C_CLASSES 10
#define BN_EPS    1e-5f
#define INV_SQRT2 0.70710678118654752440f

// ---------------- scratch ----------------
__device__ float g_bufA[(size_t)N_NODES * H_DIM];
__device__ float g_bufB[(size_t)N_NODES * H_DIM];
__device__ float g_X[(size_t)(N_NODES / 2) * H_DIM];
__device__ float g_embraw[G_GRAPHS * H_DIM];
__device__ float g_embcat[G_GRAPHS * L_LAYERS * H_DIM];
__device__ float g_stats[2 * H_DIM];
__device__ float g_scale[H_DIM];
__device__ float g_shift[H_DIM];
__device__ __nv_bfloat16 g_wimg[7 * 2 * 16384];   // [7 weights][hi|lo][K=128][N=128]

// ---------------- helpers ----------------
__device__ __forceinline__ uint32_t smem_u32(const void* p) {
    uint32_t a;
    asm("{ .reg .u64 t; cvta.to.shared.u64 t, %1; cvt.u32.u64 %0, t; }" : "=r"(a) : "l"(p));
    return a;
}
__device__ __forceinline__ uint32_t pack2(__nv_bfloat16 a, __nv_bfloat16 b) {
    __nv_bfloat162 t; t.x = a; t.y = b; return *(uint32_t*)&t;
}
#define LDSM_X4(r, a) \
    asm volatile("ldmatrix.sync.aligned.m8n8.x4.shared.b16 {%0,%1,%2,%3}, [%4];" \
        : "=r"((r)[0]), "=r"((r)[1]), "=r"((r)[2]), "=r"((r)[3]) : "r"(a))
#define LDSM_X4T(r, a) \
    asm volatile("ldmatrix.sync.aligned.m8n8.x4.trans.shared.b16 {%0,%1,%2,%3}, [%4];" \
        : "=r"((r)[0]), "=r"((r)[1]), "=r"((r)[2]), "=r"((r)[3]) : "r"(a))
#define MMA_BF16(d, a, b0, b1) \
    asm volatile("mma.sync.aligned.m16n8k16.row.col.f32.bf16.bf16.f32 " \
        "{%0,%1,%2,%3}, {%4,%5,%6,%7}, {%8,%9}, {%0,%1,%2,%3};" \
        : "+f"((d)[0]), "+f"((d)[1]), "+f"((d)[2]), "+f"((d)[3]) \
        : "r"((a)[0]), "r"((a)[1]), "r"((a)[2]), "r"((a)[3]), "r"(b0), "r"(b1))

// smem layout for tc_gemm: padded bf16 tiles, stride 136 elems = 272 B/row
#define SK_BYTES  272
#define SA_HI     0
#define SA_LO     34816
#define SB_HI     69632
#define SB_LO     104448
#define SO_BIAS   139264
#define SO_SCALE  139776
#define SO_SHIFT  140288
#define TC_SMEM   140800

// ---------------- zero stats ----------------
__global__ void zero_stats_kernel(float* stats) { stats[threadIdx.x] = 0.f; }

// ---------------- weight bf16 split (plain [K][N] layout, no transpose) -------
__global__ void transw_kernel(const float* __restrict__ w0, const float* __restrict__ w1,
                              const float* __restrict__ w2, __nv_bfloat16* __restrict__ img) {
    int b = blockIdx.x;
    const float* W = (b == 0) ? w0 : ((b <= 3) ? w1 + (size_t)(b - 1) * 16384
                                               : w2 + (size_t)(b - 4) * 16384);
    __nv_bfloat16* hi = img + (size_t)b * 32768;
    __nv_bfloat16* lo = hi + 16384;
    for (int i = threadIdx.x; i < 16384; i += blockDim.x) {
        float v = W[i];
        __nv_bfloat16 h = __float2bfloat16(v);
        hi[i] = h;
        lo[i] = __float2bfloat16(v - __bfloat162float(h));
    }
}

// ---------------- tensor-core GEMM: C[128b x 128] = op(A) @ W + bias, + stats --
// op(A) = A (mode 0) or relu(A*scale + shift) (mode 1). 3-term bf16 split.
__global__ __launch_bounds__(256) void tc_gemm(
    const float* __restrict__ A, const __nv_bfloat16* __restrict__ Wimg,
    const float* __restrict__ bias, const float* __restrict__ scale,
    const float* __restrict__ shift, int mode,
    float* __restrict__ C, float* __restrict__ stats) {
    extern __shared__ char smem[];
    const uint32_t sb = smem_u32(smem);
    const int tid = threadIdx.x, wid = tid >> 5, lane = tid & 31;
    const int wm = wid >> 1, wn = wid & 1;   // 4x2 warp grid

    float* sbias  = (float*)(smem + SO_BIAS);
    float* sscale = (float*)(smem + SO_SCALE);
    float* sshift = (float*)(smem + SO_SHIFT);
    if (tid < 128) {
        sbias[tid] = bias[tid];
        if (mode) { sscale[tid] = scale[tid]; sshift[tid] = shift[tid]; }
    }
    __syncthreads();

    // B: copy pre-split bf16 weight images into padded smem [K][136]
    {
        const uint4* bh = (const uint4*)Wimg;   // 2048 uint4 hi, then 2048 lo
        #pragma unroll
        for (int it = 0; it < 8; it++) {
            int i = tid + it * 256;
            int k = i >> 4, g = i & 15;
            uint32_t off = (uint32_t)k * SK_BYTES + (uint32_t)g * 16;
            *(uint4*)(smem + SB_HI + off) = bh[i];
            *(uint4*)(smem + SB_LO + off) = bh[2048 + i];
        }
    }
    // A: fp32 load, optional BN+relu, bf16 hi/lo split into padded smem [M][136]
    {
        const float4* A4 = (const float4*)(A + (size_t)blockIdx.x * 128 * 128);
        #pragma unroll
        for (int it = 0; it < 8; it++) {
            int i = tid + it * 256;          // 2048 groups of 8 floats
            int row = i >> 4, gk = i & 15;
            float4 u = A4[row * 32 + gk * 2];
            float4 v = A4[row * 32 + gk * 2 + 1];
            float xv[8] = {u.x, u.y, u.z, u.w, v.x, v.y, v.z, v.w};
            if (mode) {
                int c0 = gk * 8;
                #pragma unroll
                for (int j = 0; j < 8; j++)
                    xv[j] = fmaxf(fmaf(xv[j], sscale[c0 + j], sshift[c0 + j]), 0.f);
            }
            uint32_t hp[4], lp[4];
            #pragma unroll
            for (int j = 0; j < 4; j++) {
                __nv_bfloat16 h0 = __float2bfloat16(xv[2 * j]);
                __nv_bfloat16 h1 = __float2bfloat16(xv[2 * j + 1]);
                hp[j] = pack2(h0, h1);
                lp[j] = pack2(__float2bfloat16(xv[2 * j]     - __bfloat162float(h0)),
                              __float2bfloat16(xv[2 * j + 1] - __bfloat162float(h1)));
            }
            uint32_t off = (uint32_t)row * SK_BYTES + (uint32_t)gk * 16;
            *(uint4*)(smem + SA_HI + off) = make_uint4(hp[0], hp[1], hp[2], hp[3]);
            *(uint4*)(smem + SA_LO + off) = make_uint4(lp[0], lp[1], lp[2], lp[3]);
        }
    }
    __syncthreads();

    // ---------------- mainloop: m16n8k16 tiles ----------------
    float acc[2][8][4];
    #pragma unroll
    for (int mt = 0; mt < 2; mt++)
        #pragma unroll
        for (int nt = 0; nt < 8; nt++)
            #pragma unroll
            for (int j = 0; j < 4; j++) acc[mt][nt][j] = 0.f;

    // ldmatrix lane addresses
    const uint32_t aA = sb + SA_HI + (uint32_t)(wm * 32 + (lane & 15)) * SK_BYTES
                      + (uint32_t)(lane >> 4) * 16;
    const uint32_t aB = sb + SB_HI + (uint32_t)(lane & 15) * SK_BYTES
                      + (uint32_t)(wn * 64) * 2 + (uint32_t)(lane >> 4) * 16;

    #pragma unroll
    for (int ks = 0; ks < 8; ks++) {
        uint32_t ah[2][4], al[2][4], bh[4][4], bl[4][4];
        #pragma unroll
        for (int mt = 0; mt < 2; mt++) {
            uint32_t ad = aA + (uint32_t)mt * (16 * SK_BYTES) + (uint32_t)ks * 32;
            LDSM_X4(ah[mt], ad);
            LDSM_X4(al[mt], ad + (SA_LO - SA_HI));
        }
        #pragma unroll
        for (int nt2 = 0; nt2 < 4; nt2++) {
            uint32_t bd = aB + (uint32_t)ks * (16 * SK_BYTES) + (uint32_t)nt2 * 32;
            LDSM_X4T(bh[nt2], bd);
            LDSM_X4T(bl[nt2], bd + (SB_LO - SB_HI));
        }
        #pragma unroll
        for (int mt = 0; mt < 2; mt++)
            #pragma unroll
            for (int nt = 0; nt < 8; nt++) {
                uint32_t bh0 = bh[nt >> 1][(nt & 1) * 2], bh1 = bh[nt >> 1][(nt & 1) * 2 + 1];
                uint32_t bl0 = bl[nt >> 1][(nt & 1) * 2], bl1 = bl[nt >> 1][(nt & 1) * 2 + 1];
                MMA_BF16(acc[mt][nt], ah[mt], bh0, bh1);   // hi*hi
                MMA_BF16(acc[mt][nt], ah[mt], bl0, bl1);   // hi*lo
                MMA_BF16(acc[mt][nt], al[mt], bh0, bh1);   // lo*hi
            }
    }

    // ---------------- epilogue: bias + stats + coalesced C stores --------------
    float s[8][2], q[8][2];
    #pragma unroll
    for (int nt = 0; nt < 8; nt++) { s[nt][0] = s[nt][1] = q[nt][0] = q[nt][1] = 0.f; }

    const int cbase = wn * 64 + (lane & 3) * 2;
    const int rbase = wm * 32 + (lane >> 2);
    float* Cb = C + (size_t)blockIdx.x * 128 * 128;

    #pragma unroll
    for (int mt = 0; mt < 2; mt++) {
        int r0 = rbase + mt * 16, r1 = r0 + 8;
        #pragma unroll
        for (int nt = 0; nt < 8; nt++) {
            int c = cbase + nt * 8;
            float b0 = sbias[c], b1 = sbias[c + 1];
            float y0 = acc[mt][nt][0] + b0, y1 = acc[mt][nt][1] + b1;
            float y2 = acc[mt][nt][2] + b0, y3 = acc[mt][nt][3] + b1;
            s[nt][0] += y0 + y2;           s[nt][1] += y1 + y3;
            q[nt][0] += y0 * y0 + y2 * y2; q[nt][1] += y1 * y1 + y3 * y3;
            *(float2*)(Cb + r0 * 128 + c) = make_float2(y0, y1);
            *(float2*)(Cb + r1 * 128 + c) = make_float2(y2, y3);
        }
    }
    // reduce over the 8 lanes sharing (lane & 3) -> lanes 0..3 hold column totals
    #pragma unroll
    for (int off = 16; off >= 4; off >>= 1)
        #pragma unroll
        for (int nt = 0; nt < 8; nt++) {
            s[nt][0] += __shfl_down_sync(0xFFFFFFFFu, s[nt][0], off);
            s[nt][1] += __shfl_down_sync(0xFFFFFFFFu, s[nt][1], off);
            q[nt][0] += __shfl_down_sync(0xFFFFFFFFu, q[nt][0], off);
            q[nt][1] += __shfl_down_sync(0xFFFFFFFFu, q[nt][1], off);
        }
    if (lane < 4) {
        #pragma unroll
        for (int nt = 0; nt < 8; nt++) {
            int c = cbase + nt * 8;
            atomicAdd(&stats[c],           s[nt][0]);
            atomicAdd(&stats[c + 1],       s[nt][1]);
            atomicAdd(&stats[128 + c],     q[nt][0]);
            atomicAdd(&stats[128 + c + 1], q[nt][1]);
        }
    }
}

// ---------------- BN finalize ----------------
__global__ void finalize_kernel(const float* __restrict__ gw, const float* __restrict__ bw,
                                float n, float* __restrict__ scale, float* __restrict__ shift,
                                float* __restrict__ stats) {
    int c = threadIdx.x;
    float sv = stats[c], qv = stats[128 + c];
    float m = sv / n;
    float v = qv / n - m * m;
    float sc = gw[c] * rsqrtf(v + BN_EPS);
    scale[c] = sc;
    shift[c] = fmaf(-m, sc, bw[c]);
    stats[c] = 0.f;
    stats[128 + c] = 0.f;
}

// ---------------- GIN aggregation (block per graph, CSR in smem) ---------------
__global__ __launch_bounds__(256) void agg_kernel(
    const float* __restrict__ X, const int* __restrict__ src, const int* __restrict__ dst,
    const float* __restrict__ scale, const float* __restrict__ shift, int mode,
    float* __restrict__ Hout, int npg, int shiftbits) {
    extern __shared__ float sm[];
    float* xs  = sm;
    int*   cnt = (int*)(sm + npg * 128);    // npg+1
    int*   cur = cnt + npg + 1;             // npg
    int*   ssrc = cur + npg;                // EPG

    const int g = blockIdx.x, tid = threadIdx.x;
    const float4* X4 = (const float4*)(X + (size_t)g * npg * 128);
    const int nv = npg * 32;

    if (mode) {
        for (int i = tid; i < nv; i += 256) {
            float4 v = X4[i];
            int c = (i & 31) * 4;
            v.x = fmaxf(fmaf(v.x, scale[c + 0], shift[c + 0]), 0.f);
            v.y = fmaxf(fmaf(v.y, scale[c + 1], shift[c + 1]), 0.f);
            v.z = fmaxf(fmaf(v.z, scale[c + 2], shift[c + 2]), 0.f);
            v.w = fmaxf(fmaf(v.w, scale[c + 3], shift[c + 3]), 0.f);
            ((float4*)xs)[i] = v;
        }
    } else {
        for (int i = tid; i < nv; i += 256) ((float4*)xs)[i] = X4[i];
    }
    for (int i = tid; i <= npg; i += 256) cnt[i] = 0;
    __syncthreads();

    const int ebase = g * EPG, nb = g * NPG0;
    for (int e = tid; e < EPG; e += 256) {
        int d = (dst[ebase + e] - nb) >> shiftbits;
        atomicAdd(&cnt[d], 1);
    }
    __syncthreads();
    // inclusive scan (Hillis-Steele)
    for (int off = 1; off < npg; off <<= 1) {
        int v = 0;
        if (tid < npg && tid >= off) v = cnt[tid - off];
        __syncthreads();
        if (tid < npg) cnt[tid] += v;
        __syncthreads();
    }
    if (tid < npg) cur[tid] = tid ? cnt[tid - 1] : 0;
    __syncthreads();
    for (int e = tid; e < EPG; e += 256) {
        int d  = (dst[ebase + e] - nb) >> shiftbits;
        int sl = (src[ebase + e] - nb) >> shiftbits;
        int p = atomicAdd(&cur[d], 1);
        ssrc[p] = sl;
    }
    __syncthreads();

    const int warp = tid >> 5, lane = tid & 31;
    const float4* xs4 = (const float4*)xs;
    float4* H4 = (float4*)(Hout + (size_t)g * npg * 128);
    for (int d = warp; d < npg; d += 8) {
        float4 a = xs4[d * 32 + lane];
        float4 b = make_float4(0.f, 0.f, 0.f, 0.f);
        int e0 = d ? cnt[d - 1] : 0, e1 = cnt[d];
        int p = e0;
        for (; p + 1 < e1; p += 2) {
            float4 v1 = xs4[ssrc[p] * 32 + lane];
            float4 v2 = xs4[ssrc[p + 1] * 32 + lane];
            a.x += v1.x; a.y += v1.y; a.z += v1.z; a.w += v1.w;
            b.x += v2.x; b.y += v2.y; b.z += v2.z; b.w += v2.w;
        }
        if (p < e1) {
            float4 v1 = xs4[ssrc[p] * 32 + lane];
            a.x += v1.x; a.y += v1.y; a.z += v1.z; a.w += v1.w;
        }
        a.x += b.x; a.y += b.y; a.z += b.z; a.w += b.w;
        H4[d * 32 + lane] = a;
    }
}

// ---------------- pool ----------------
__global__ __launch_bounds__(256) void pool_kernel(
    const float* __restrict__ Hin, const float* __restrict__ sc, const float* __restrict__ sh,
    float* __restrict__ Xout, float* __restrict__ embraw, float* __restrict__ stats, int npg_in) {
    __shared__ float es[128];
    const int g = blockIdx.x, tid = threadIdx.x;
    if (tid < 128) es[tid] = 0.f;
    __syncthreads();

    const int npg_out = npg_in >> 1;
    const float4* in4 = (const float4*)(Hin + (size_t)g * npg_in * 128);
    float4* out4 = (float4*)(Xout + (size_t)g * npg_out * 128);

    for (int i = tid; i < npg_out * 32; i += 256) {
        int row = i >> 5, c4 = i & 31, c = c4 * 4;
        float4 a = in4[(2 * row) * 32 + c4];
        float4 b = in4[(2 * row + 1) * 32 + c4];
        float4 p;
        p.x = (fmaxf(fmaf(a.x, sc[c+0], sh[c+0]), 0.f) + fmaxf(fmaf(b.x, sc[c+0], sh[c+0]), 0.f)) * INV_SQRT2;
        p.y = (fmaxf(fmaf(a.y, sc[c+1], sh[c+1]), 0.f) + fmaxf(fmaf(b.y, sc[c+1], sh[c+1]), 0.f)) * INV_SQRT2;
        p.z = (fmaxf(fmaf(a.z, sc[c+2], sh[c+2]), 0.f) + fmaxf(fmaf(b.z, sc[c+2], sh[c+2]), 0.f)) * INV_SQRT2;
        p.w = (fmaxf(fmaf(a.w, sc[c+3], sh[c+3]), 0.f) + fmaxf(fmaf(b.w, sc[c+3], sh[c+3]), 0.f)) * INV_SQRT2;
        out4[i] = p;
        atomicAdd(&es[c + 0], p.x);
        atomicAdd(&es[c + 1], p.y);
        atomicAdd(&es[c + 2], p.z);
        atomicAdd(&es[c + 3], p.w);
    }
    __syncthreads();
    if (tid < 128) {
        float v = es[tid];
        embraw[g * 128 + tid] = v;
        atomicAdd(&stats[tid], v);
        atomicAdd(&stats[128 + tid], v * v);
    }
}

// ---------------- embedding BN apply ----------------
__global__ void eapply_kernel(const float* __restrict__ raw, const float* __restrict__ sc,
                              const float* __restrict__ sh, float* __restrict__ cat, int layer) {
    int idx = blockIdx.x * blockDim.x + threadIdx.x;
    if (idx < G_GRAPHS * H_DIM) {
        int g = idx >> 7, c = idx & 127;
        float v = fmaxf(fmaf(raw[idx], sc[c], sh[c]), 0.f);
        cat[g * (L_LAYERS * H_DIM) + layer * H_DIM + c] = v;
    }
}

// ---------------- final linear ----------------
__global__ void final_linear_kernel(const float* __restrict__ emb, const float* __restrict__ W,
                                    const float* __restrict__ b, float* __restrict__ out) {
    const int g = blockIdx.x, lane = threadIdx.x;
    float acc[C_CLASSES];
    #pragma unroll
    for (int c = 0; c < C_CLASSES; c++) acc[c] = 0.f;
    for (int k = lane; k < L_LAYERS * H_DIM; k += 32) {
        float e = emb[g * (L_LAYERS * H_DIM) + k];
        #pragma unroll
        for (int c = 0; c < C_CLASSES; c++)
            acc[c] = fmaf(e, W[k * C_CLASSES + c], acc[c]);
    }
    #pragma unroll
    for (int off = 16; off > 0; off >>= 1)
        #pragma unroll
        for (int c = 0; c < C_CLASSES; c++)
            acc[c] += __shfl_down_sync(0xFFFFFFFFu, acc[c], off);
    if (lane == 0) {
        #pragma unroll
        for (int c = 0; c < C_CLASSES; c++)
            out[g * C_CLASSES + c] = acc[c] + b[c];
    }
}

// ---------------- host orchestration ----------------
extern "C" void kernel_launch(void* const* d_in, const int* in_sizes, int n_in,
                              void* d_out, int out_size) {
    const float* x           = (const float*)d_in[0];
    const int*   ei          = (const int*)d_in[1];
    const int*   src         = ei;
    const int*   dst         = ei + E_EDGES;
    const float* lin_start_w = (const float*)d_in[2];
    const float* lin_start_b = (const float*)d_in[3];
    const float* bn_start_g  = (const float*)d_in[4];
    const float* bn_start_b  = (const float*)d_in[5];
    const float* conv_w1     = (const float*)d_in[6];
    const float* conv_b1     = (const float*)d_in[7];
    const float* conv_bn_g   = (const float*)d_in[8];
    const float* conv_bn_b   = (const float*)d_in[9];
    const float* conv_w2     = (const float*)d_in[10];
    const float* conv_b2     = (const float*)d_in[11];
    const float* bn_g        = (const float*)d_in[12];
    const float* bn_b        = (const float*)d_in[13];
    const float* bne_g       = (const float*)d_in[14];
    const float* bne_b       = (const float*)d_in[15];
    const float* lin_w       = (const float*)d_in[16];
    const float* lin_b       = (const float*)d_in[17];
    float* out = (float*)d_out;

    float *bufA, *bufB, *bufX, *embraw, *embcat, *stats, *scale, *shift;
    __nv_bfloat16* wimg;
    cudaGetSymbolAddress((void**)&bufA,   g_bufA);
    cudaGetSymbolAddress((void**)&bufB,   g_bufB);
    cudaGetSymbolAddress((void**)&bufX,   g_X);
    cudaGetSymbolAddress((void**)&embraw, g_embraw);
    cudaGetSymbolAddress((void**)&embcat, g_embcat);
    cudaGetSymbolAddress((void**)&stats,  g_stats);
    cudaGetSymbolAddress((void**)&scale,  g_scale);
    cudaGetSymbolAddress((void**)&shift,  g_shift);
    cudaGetSymbolAddress((void**)&wimg,   g_wimg);

    cudaFuncSetAttribute(tc_gemm, cudaFuncAttributeMaxDynamicSharedMemorySize, TC_SMEM);
    const int agg_smem0 = NPG0 * 128 * 4 + (2 * NPG0 + 1) * 4 + EPG * 4;
    cudaFuncSetAttribute(agg_kernel, cudaFuncAttributeMaxDynamicSharedMemorySize, agg_smem0);

    zero_stats_kernel<<<1, 256>>>(stats);
    transw_kernel<<<7, 256>>>(lin_start_w, conv_w1, conv_w2, wimg);

    // Stage 0: Y0 = x @ W_start + b (stats fused)
    tc_gemm<<<N_NODES / 128, 256, TC_SMEM>>>(
        x, wimg, lin_start_b, nullptr, nullptr, 0, bufA, stats);
    finalize_kernel<<<1, 128>>>(bn_start_g, bn_start_b, (float)N_NODES, scale, shift, stats);

    for (int i = 0; i < L_LAYERS; i++) {
        const int n   = N_NODES >> i;
        const int npg = NPG0 >> i;
        const int agg_smem = npg * 128 * 4 + (2 * npg + 1) * 4 + EPG * 4;

        const float* ain = (i == 0) ? (const float*)bufA : (const float*)bufX;
        agg_kernel<<<G_GRAPHS, 256, agg_smem>>>(
            ain, src, dst, scale, shift, (i == 0) ? 1 : 0, bufB, npg, i);

        tc_gemm<<<n / 128, 256, TC_SMEM>>>(
            bufB, wimg + (size_t)(1 + i) * 32768, conv_b1 + i * H_DIM,
            nullptr, nullptr, 0, bufA, stats);
        finalize_kernel<<<1, 128>>>(conv_bn_g + i * H_DIM, conv_bn_b + i * H_DIM,
                                    (float)n, scale, shift, stats);

        tc_gemm<<<n / 128, 256, TC_SMEM>>>(
            bufA, wimg + (size_t)(4 + i) * 32768, conv_b2 + i * H_DIM,
            scale, shift, 1, bufB, stats);
        finalize_kernel<<<1, 128>>>(bn_g + i * H_DIM, bn_b + i * H_DIM,
                                    (float)n, scale, shift, stats);

        pool_kernel<<<G_GRAPHS, 256>>>(bufB, scale, shift, bufX, embraw, stats, npg);
        finalize_kernel<<<1, 128>>>(bne_g + i * H_DIM, bne_b + i * H_DIM,
                                    (float)G_GRAPHS, scale, shift, stats);
        eapply_kernel<<<(G_GRAPHS * H_DIM + 255) / 256, 256>>>(embraw, scale, shift, embcat, i);
    }

    final_linear_kernel<<<G_GRAPHS, 32>>>(embcat, lin_w, lin_b, out);
}

// round 5
// speedup vs baseline: 1.2948x; 1.1410x over previous
#include <cuda_runtime.h>
#include <cuda_bf16.h>
#include <math.h>
#include <stdint.h>

// ---------------- problem constants ----------------
#define N_NODES   131072
#define G_GRAPHS  1024
#define NPG0      128
#define H_DIM     128
#define E_EDGES   2097152
#define EPG       2048
#define L_LAYERS  3
#define C_CLASSES 10
#define BN_EPS    1e-5f
#define INV_SQRT2 0.70710678118654752440f
#define N_SLOTS   10

// ---------------- scratch ----------------
__device__ float g_bufA[(size_t)N_NODES * H_DIM];
__device__ float g_bufB[(size_t)N_NODES * H_DIM];   // also reused as bf16 Y planes
__device__ float g_X[(size_t)(N_NODES / 2) * H_DIM];
__device__ float g_embraw[G_GRAPHS * H_DIM];
__device__ float g_embcat[G_GRAPHS * L_LAYERS * H_DIM];
__device__ float g_statsAll[N_SLOTS * 256];          // per-stage [sum(128), sumsq(128)]
__device__ __nv_bfloat16 g_wimg[7 * 2 * 16384];      // [7 weights][hi|lo][K=128][N=128]

// ---------------- helpers ----------------
__device__ __forceinline__ uint32_t smem_u32(const void* p) {
    uint32_t a;
    asm("{ .reg .u64 t; cvta.to.shared.u64 t, %1; cvt.u32.u64 %0, t; }" : "=r"(a) : "l"(p));
    return a;
}
__device__ __forceinline__ uint32_t pack2(__nv_bfloat16 a, __nv_bfloat16 b) {
    __nv_bfloat162 t; t.x = a; t.y = b; return *(uint32_t*)&t;
}
#define LDSM_X4(r, a) \
    asm volatile("ldmatrix.sync.aligned.m8n8.x4.shared.b16 {%0,%1,%2,%3}, [%4];" \
        : "=r"((r)[0]), "=r"((r)[1]), "=r"((r)[2]), "=r"((r)[3]) : "r"(a))
#define LDSM_X4T(r, a) \
    asm volatile("ldmatrix.sync.aligned.m8n8.x4.trans.shared.b16 {%0,%1,%2,%3}, [%4];" \
        : "=r"((r)[0]), "=r"((r)[1]), "=r"((r)[2]), "=r"((r)[3]) : "r"(a))
#define MMA_BF16(d, a, b0, b1) \
    asm volatile("mma.sync.aligned.m16n8k16.row.col.f32.bf16.bf16.f32 " \
        "{%0,%1,%2,%3}, {%4,%5,%6,%7}, {%8,%9}, {%0,%1,%2,%3};" \
        : "+f"((d)[0]), "+f"((d)[1]), "+f"((d)[2]), "+f"((d)[3]) \
        : "r"((a)[0]), "r"((a)[1]), "r"((a)[2]), "r"((a)[3]), "r"(b0), "r"(b1))

// bf16 tiles padded to stride 136 elems = 272 B/row (conflict-free ldmatrix)
#define SK_BYTES  272

// ---- tc_gemm smem layout ----
#define SA_HI     0
#define SA_LO     34816
#define SB_HI     69632
#define SB_LO     104448
#define SO_BIAS   139264
#define SO_SCALE  139776
#define SO_SHIFT  140288
#define TC_SMEM   140800

// ---- agg_mma smem layout ----
#define AG_CNT    0         // 128x128 int = 65536
#define AG_AT     65536     // 34816
#define AG_BH     100352    // 34816
#define AG_BL     135168    // 34816
#define AG_BIAS   169984    // 512
#define AG_SMEM   170496

// ---------------- weight bf16 split + stats zero ----------------
__global__ void transw_kernel(const float* __restrict__ w0, const float* __restrict__ w1,
                              const float* __restrict__ w2, __nv_bfloat16* __restrict__ img,
                              float* __restrict__ statsAll) {
    int b = blockIdx.x;
    if (b == 7) {
        for (int i = threadIdx.x; i < N_SLOTS * 256; i += blockDim.x) statsAll[i] = 0.f;
        return;
    }
    const float* W = (b == 0) ? w0 : ((b <= 3) ? w1 + (size_t)(b - 1) * 16384
                                               : w2 + (size_t)(b - 4) * 16384);
    __nv_bfloat16* hi = img + (size_t)b * 32768;
    __nv_bfloat16* lo = hi + 16384;
    for (int i = threadIdx.x; i < 16384; i += blockDim.x) {
        float v = W[i];
        __nv_bfloat16 h = __float2bfloat16(v);
        hi[i] = h;
        lo[i] = __float2bfloat16(v - __bfloat162float(h));
    }
}

// ---------------- tensor-core GEMM ----------------
// C = op(A) @ W [+ bias]; op = identity (mode 0) or BN+relu with coefs computed
// inline from statsIn (mode 1). owhich=0: fp32 C + bias + stats. owhich=1: bf16
// hi/lo planes, no bias, no stats.
__global__ __launch_bounds__(256) void tc_gemm(
    const float* __restrict__ A, const __nv_bfloat16* __restrict__ Wimg,
    const float* __restrict__ bias,
    const float* __restrict__ bnG, const float* __restrict__ bnB,
    const float* __restrict__ statsIn, float nIn, int mode,
    float* __restrict__ Cf, __nv_bfloat16* __restrict__ Yhi, __nv_bfloat16* __restrict__ Ylo,
    int owhich, float* __restrict__ statsOut) {
    extern __shared__ char smem[];
    const uint32_t sb = smem_u32(smem);
    const int tid = threadIdx.x, wid = tid >> 5, lane = tid & 31;
    const int wm = wid >> 1, wn = wid & 1;

    float* sbias  = (float*)(smem + SO_BIAS);
    float* sscale = (float*)(smem + SO_SCALE);
    float* sshift = (float*)(smem + SO_SHIFT);
    if (tid < 128) {
        if (owhich == 0) sbias[tid] = bias[tid];
        if (mode) {
            float s = statsIn[tid], q = statsIn[128 + tid];
            float m = s / nIn, v = q / nIn - m * m;
            float sc = bnG[tid] * rsqrtf(v + BN_EPS);
            sscale[tid] = sc;
            sshift[tid] = fmaf(-m, sc, bnB[tid]);
        }
    }
    __syncthreads();

    // B: pre-split bf16 weight images -> padded smem [K][136]
    {
        const uint4* bh = (const uint4*)Wimg;
        #pragma unroll
        for (int it = 0; it < 8; it++) {
            int i = tid + it * 256;
            int k = i >> 4, g = i & 15;
            uint32_t off = (uint32_t)k * SK_BYTES + (uint32_t)g * 16;
            *(uint4*)(smem + SB_HI + off) = bh[i];
            *(uint4*)(smem + SB_LO + off) = bh[2048 + i];
        }
    }
    // A: fp32 load, optional BN+relu, hi/lo split -> padded smem [M][136]
    {
        const float4* A4 = (const float4*)(A + (size_t)blockIdx.x * 128 * 128);
        #pragma unroll
        for (int it = 0; it < 8; it++) {
            int i = tid + it * 256;
            int row = i >> 4, gk = i & 15;
            float4 u = A4[row * 32 + gk * 2];
            float4 v = A4[row * 32 + gk * 2 + 1];
            float xv[8] = {u.x, u.y, u.z, u.w, v.x, v.y, v.z, v.w};
            if (mode) {
                int c0 = gk * 8;
                #pragma unroll
                for (int j = 0; j < 8; j++)
                    xv[j] = fmaxf(fmaf(xv[j], sscale[c0 + j], sshift[c0 + j]), 0.f);
            }
            uint32_t hp[4], lp[4];
            #pragma unroll
            for (int j = 0; j < 4; j++) {
                __nv_bfloat16 h0 = __float2bfloat16(xv[2 * j]);
                __nv_bfloat16 h1 = __float2bfloat16(xv[2 * j + 1]);
                hp[j] = pack2(h0, h1);
                lp[j] = pack2(__float2bfloat16(xv[2 * j]     - __bfloat162float(h0)),
                              __float2bfloat16(xv[2 * j + 1] - __bfloat162float(h1)));
            }
            uint32_t off = (uint32_t)row * SK_BYTES + (uint32_t)gk * 16;
            *(uint4*)(smem + SA_HI + off) = make_uint4(hp[0], hp[1], hp[2], hp[3]);
            *(uint4*)(smem + SA_LO + off) = make_uint4(lp[0], lp[1], lp[2], lp[3]);
        }
    }
    __syncthreads();

    float acc[2][8][4];
    #pragma unroll
    for (int mt = 0; mt < 2; mt++)
        #pragma unroll
        for (int nt = 0; nt < 8; nt++)
            #pragma unroll
            for (int j = 0; j < 4; j++) acc[mt][nt][j] = 0.f;

    const uint32_t aA = sb + SA_HI + (uint32_t)(wm * 32 + (lane & 15)) * SK_BYTES
                      + (uint32_t)(lane >> 4) * 16;
    const uint32_t aB = sb + SB_HI + (uint32_t)(lane & 15) * SK_BYTES
                      + (uint32_t)(wn * 128) + (uint32_t)(lane >> 4) * 16;

    #pragma unroll
    for (int ks = 0; ks < 8; ks++) {
        uint32_t ah[2][4], al[2][4], bh[4][4], bl[4][4];
        #pragma unroll
        for (int mt = 0; mt < 2; mt++) {
            uint32_t ad = aA + (uint32_t)mt * (16 * SK_BYTES) + (uint32_t)ks * 32;
            LDSM_X4(ah[mt], ad);
            LDSM_X4(al[mt], ad + (SA_LO - SA_HI));
        }
        #pragma unroll
        for (int nt2 = 0; nt2 < 4; nt2++) {
            uint32_t bd = aB + (uint32_t)ks * (16 * SK_BYTES) + (uint32_t)nt2 * 32;
            LDSM_X4T(bh[nt2], bd);
            LDSM_X4T(bl[nt2], bd + (SB_LO - SB_HI));
        }
        #pragma unroll
        for (int mt = 0; mt < 2; mt++)
            #pragma unroll
            for (int nt = 0; nt < 8; nt++) {
                uint32_t bh0 = bh[nt >> 1][(nt & 1) * 2], bh1 = bh[nt >> 1][(nt & 1) * 2 + 1];
                uint32_t bl0 = bl[nt >> 1][(nt & 1) * 2], bl1 = bl[nt >> 1][(nt & 1) * 2 + 1];
                MMA_BF16(acc[mt][nt], ah[mt], bh0, bh1);
                MMA_BF16(acc[mt][nt], ah[mt], bl0, bl1);
                MMA_BF16(acc[mt][nt], al[mt], bh0, bh1);
            }
    }

    const int cbase = wn * 64 + (lane & 3) * 2;
    const int rbase = wm * 32 + (lane >> 2);

    if (owhich == 1) {
        // store as bf16 hi/lo planes
        __nv_bfloat16* Ph = Yhi + (size_t)blockIdx.x * 128 * 128;
        __nv_bfloat16* Pl = Ylo + (size_t)blockIdx.x * 128 * 128;
        #pragma unroll
        for (int mt = 0; mt < 2; mt++) {
            int r0 = rbase + mt * 16, r1 = r0 + 8;
            #pragma unroll
            for (int nt = 0; nt < 8; nt++) {
                int c = cbase + nt * 8;
                float y0 = acc[mt][nt][0], y1 = acc[mt][nt][1];
                float y2 = acc[mt][nt][2], y3 = acc[mt][nt][3];
                __nv_bfloat16 h0 = __float2bfloat16(y0), h1 = __float2bfloat16(y1);
                __nv_bfloat16 h2 = __float2bfloat16(y2), h3 = __float2bfloat16(y3);
                *(uint32_t*)(Ph + r0 * 128 + c) = pack2(h0, h1);
                *(uint32_t*)(Ph + r1 * 128 + c) = pack2(h2, h3);
                *(uint32_t*)(Pl + r0 * 128 + c) =
                    pack2(__float2bfloat16(y0 - __bfloat162float(h0)),
                          __float2bfloat16(y1 - __bfloat162float(h1)));
                *(uint32_t*)(Pl + r1 * 128 + c) =
                    pack2(__float2bfloat16(y2 - __bfloat162float(h2)),
                          __float2bfloat16(y3 - __bfloat162float(h3)));
            }
        }
        return;
    }

    // fp32 out + bias + stats
    float s[8][2], q[8][2];
    #pragma unroll
    for (int nt = 0; nt < 8; nt++) { s[nt][0] = s[nt][1] = q[nt][0] = q[nt][1] = 0.f; }
    float* Cb = Cf + (size_t)blockIdx.x * 128 * 128;
    #pragma unroll
    for (int mt = 0; mt < 2; mt++) {
        int r0 = rbase + mt * 16, r1 = r0 + 8;
        #pragma unroll
        for (int nt = 0; nt < 8; nt++) {
            int c = cbase + nt * 8;
            float b0 = sbias[c], b1 = sbias[c + 1];
            float y0 = acc[mt][nt][0] + b0, y1 = acc[mt][nt][1] + b1;
            float y2 = acc[mt][nt][2] + b0, y3 = acc[mt][nt][3] + b1;
            s[nt][0] += y0 + y2;           s[nt][1] += y1 + y3;
            q[nt][0] += y0 * y0 + y2 * y2; q[nt][1] += y1 * y1 + y3 * y3;
            *(float2*)(Cb + r0 * 128 + c) = make_float2(y0, y1);
            *(float2*)(Cb + r1 * 128 + c) = make_float2(y2, y3);
        }
    }
    #pragma unroll
    for (int off = 16; off >= 4; off >>= 1)
        #pragma unroll
        for (int nt = 0; nt < 8; nt++) {
            s[nt][0] += __shfl_down_sync(0xFFFFFFFFu, s[nt][0], off);
            s[nt][1] += __shfl_down_sync(0xFFFFFFFFu, s[nt][1], off);
            q[nt][0] += __shfl_down_sync(0xFFFFFFFFu, q[nt][0], off);
            q[nt][1] += __shfl_down_sync(0xFFFFFFFFu, q[nt][1], off);
        }
    if (lane < 4) {
        #pragma unroll
        for (int nt = 0; nt < 8; nt++) {
            int c = cbase + nt * 8;
            atomicAdd(&statsOut[c],           s[nt][0]);
            atomicAdd(&statsOut[c + 1],       s[nt][1]);
            atomicAdd(&statsOut[128 + c],     q[nt][0]);
            atomicAdd(&statsOut[128 + c + 1], q[nt][1]);
        }
    }
}

// ---------------- aggregation as MMA: H = (I + A) * Y + b1, + stats ------------
// Block-diagonal packing: 2^layer graphs per 128x128 tile.
__global__ __launch_bounds__(256) void agg_mma(
    const __nv_bfloat16* __restrict__ Yhi, const __nv_bfloat16* __restrict__ Ylo,
    const int* __restrict__ src, const int* __restrict__ dst,
    const float* __restrict__ bias, float* __restrict__ H,
    float* __restrict__ statsOut, int layer) {
    extern __shared__ char smem[];
    const uint32_t sb = smem_u32(smem);
    const int tid = threadIdx.x, wid = tid >> 5, lane = tid & 31;
    const int wm = wid >> 1, wn = wid & 1;
    int* cnt = (int*)(smem + AG_CNT);
    float* sbias = (float*)(smem + AG_BIAS);
    if (tid < 128) sbias[tid] = bias[tid];

    // zero counts
    {
        int4* c4 = (int4*)cnt;
        #pragma unroll
        for (int it = 0; it < 16; it++) c4[tid + it * 256] = make_int4(0, 0, 0, 0);
    }
    // copy Y planes into padded smem [K=128][136]
    {
        const uint4* yh = (const uint4*)(Yhi + (size_t)blockIdx.x * 128 * 128);
        const uint4* yl = (const uint4*)(Ylo + (size_t)blockIdx.x * 128 * 128);
        #pragma unroll
        for (int it = 0; it < 8; it++) {
            int i = tid + it * 256;
            int k = i >> 4, g = i & 15;
            uint32_t off = (uint32_t)k * SK_BYTES + (uint32_t)g * 16;
            *(uint4*)(smem + AG_BH + off) = yh[i];
            *(uint4*)(smem + AG_BL + off) = yl[i];
        }
    }
    __syncthreads();

    // build adjacency counts (block-diagonal over 2^layer graphs)
    const int gb = 1 << layer;
    const int npg = NPG0 >> layer;
    const int g0 = blockIdx.x * gb;
    const int tot = gb * EPG;
    for (int idx = tid; idx < tot; idx += 256) {
        int j = idx >> 11;                       // EPG = 2048
        int e = (g0 + j) * EPG + (idx & 2047);
        int nb = (g0 + j) * NPG0;
        int d = (dst[e] - nb) >> layer;
        int s = (src[e] - nb) >> layer;
        atomicAdd(&cnt[(j * npg + d) * 128 + (j * npg + s)], 1);
    }
    __syncthreads();

    // counts (+I) -> bf16 A tile
    #pragma unroll
    for (int it = 0; it < 8; it++) {
        int i = tid + it * 256;
        int row = i >> 4, col8 = (i & 15) * 8;
        uint32_t p[4];
        #pragma unroll
        for (int j2 = 0; j2 < 4; j2++) {
            int c0 = col8 + j2 * 2;
            float v0 = (float)(cnt[row * 128 + c0]     + (row == c0     ? 1 : 0));
            float v1 = (float)(cnt[row * 128 + c0 + 1] + (row == c0 + 1 ? 1 : 0));
            p[j2] = pack2(__float2bfloat16(v0), __float2bfloat16(v1));
        }
        *(uint4*)(smem + AG_AT + (uint32_t)row * SK_BYTES + (uint32_t)col8 * 2)
            = make_uint4(p[0], p[1], p[2], p[3]);
    }
    __syncthreads();

    // MMA: 2 terms (A exact bf16)
    float acc[2][8][4];
    #pragma unroll
    for (int mt = 0; mt < 2; mt++)
        #pragma unroll
        for (int nt = 0; nt < 8; nt++)
            #pragma unroll
            for (int j = 0; j < 4; j++) acc[mt][nt][j] = 0.f;

    const uint32_t aA = sb + AG_AT + (uint32_t)(wm * 32 + (lane & 15)) * SK_BYTES
                      + (uint32_t)(lane >> 4) * 16;
    const uint32_t aB = sb + AG_BH + (uint32_t)(lane & 15) * SK_BYTES
                      + (uint32_t)(wn * 128) + (uint32_t)(lane >> 4) * 16;

    #pragma unroll
    for (int ks = 0; ks < 8; ks++) {
        uint32_t a[2][4], bh[4][4], bl[4][4];
        #pragma unroll
        for (int mt = 0; mt < 2; mt++)
            LDSM_X4(a[mt], aA + (uint32_t)mt * (16 * SK_BYTES) + (uint32_t)ks * 32);
        #pragma unroll
        for (int nt2 = 0; nt2 < 4; nt2++) {
            uint32_t bd = aB + (uint32_t)ks * (16 * SK_BYTES) + (uint32_t)nt2 * 32;
            LDSM_X4T(bh[nt2], bd);
            LDSM_X4T(bl[nt2], bd + (AG_BL - AG_BH));
        }
        #pragma unroll
        for (int mt = 0; mt < 2; mt++)
            #pragma unroll
            for (int nt = 0; nt < 8; nt++) {
                uint32_t bh0 = bh[nt >> 1][(nt & 1) * 2], bh1 = bh[nt >> 1][(nt & 1) * 2 + 1];
                uint32_t bl0 = bl[nt >> 1][(nt & 1) * 2], bl1 = bl[nt >> 1][(nt & 1) * 2 + 1];
                MMA_BF16(acc[mt][nt], a[mt], bh0, bh1);
                MMA_BF16(acc[mt][nt], a[mt], bl0, bl1);
            }
    }

    // epilogue: bias + stats + fp32 store
    float s[8][2], q[8][2];
    #pragma unroll
    for (int nt = 0; nt < 8; nt++) { s[nt][0] = s[nt][1] = q[nt][0] = q[nt][1] = 0.f; }
    const int cbase = wn * 64 + (lane & 3) * 2;
    const int rbase = wm * 32 + (lane >> 2);
    float* Hb = H + (size_t)blockIdx.x * 128 * 128;
    #pragma unroll
    for (int mt = 0; mt < 2; mt++) {
        int r0 = rbase + mt * 16, r1 = r0 + 8;
        #pragma unroll
        for (int nt = 0; nt < 8; nt++) {
            int c = cbase + nt * 8;
            float b0 = sbias[c], b1 = sbias[c + 1];
            float y0 = acc[mt][nt][0] + b0, y1 = acc[mt][nt][1] + b1;
            float y2 = acc[mt][nt][2] + b0, y3 = acc[mt][nt][3] + b1;
            s[nt][0] += y0 + y2;           s[nt][1] += y1 + y3;
            q[nt][0] += y0 * y0 + y2 * y2; q[nt][1] += y1 * y1 + y3 * y3;
            *(float2*)(Hb + r0 * 128 + c) = make_float2(y0, y1);
            *(float2*)(Hb + r1 * 128 + c) = make_float2(y2, y3);
        }
    }
    #pragma unroll
    for (int off = 16; off >= 4; off >>= 1)
        #pragma unroll
        for (int nt = 0; nt < 8; nt++) {
            s[nt][0] += __shfl_down_sync(0xFFFFFFFFu, s[nt][0], off);
            s[nt][1] += __shfl_down_sync(0xFFFFFFFFu, s[nt][1], off);
            q[nt][0] += __shfl_down_sync(0xFFFFFFFFu, q[nt][0], off);
            q[nt][1] += __shfl_down_sync(0xFFFFFFFFu, q[nt][1], off);
        }
    if (lane < 4) {
        #pragma unroll
        for (int nt = 0; nt < 8; nt++) {
            int c = cbase + nt * 8;
            atomicAdd(&statsOut[c],           s[nt][0]);
            atomicAdd(&statsOut[c + 1],       s[nt][1]);
            atomicAdd(&statsOut[128 + c],     q[nt][0]);
            atomicAdd(&statsOut[128 + c + 1], q[nt][1]);
        }
    }
}

// ---------------- pool: inline BN+relu -> Haar -> graph sum + embd stats -------
__global__ __launch_bounds__(256) void pool_kernel(
    const float* __restrict__ Hin,
    const float* __restrict__ bnG, const float* __restrict__ bnB,
    const float* __restrict__ statsIn, float nIn,
    float* __restrict__ Xout, float* __restrict__ embraw,
    float* __restrict__ statsOut, int npg_in) {
    __shared__ float es[128], psc[128], psh[128];
    const int g = blockIdx.x, tid = threadIdx.x;
    if (tid < 128) {
        es[tid] = 0.f;
        float sv = statsIn[tid], qv = statsIn[128 + tid];
        float m = sv / nIn, v = qv / nIn - m * m;
        float c_ = bnG[tid] * rsqrtf(v + BN_EPS);
        psc[tid] = c_;
        psh[tid] = fmaf(-m, c_, bnB[tid]);
    }
    __syncthreads();

    const int npg_out = npg_in >> 1;
    const float4* in4 = (const float4*)(Hin + (size_t)g * npg_in * 128);
    float4* out4 = (float4*)(Xout + (size_t)g * npg_out * 128);

    for (int i = tid; i < npg_out * 32; i += 256) {
        int row = i >> 5, c4 = i & 31, c = c4 * 4;
        float4 a = in4[(2 * row) * 32 + c4];
        float4 b = in4[(2 * row + 1) * 32 + c4];
        float4 p;
        p.x = (fmaxf(fmaf(a.x, psc[c+0], psh[c+0]), 0.f) + fmaxf(fmaf(b.x, psc[c+0], psh[c+0]), 0.f)) * INV_SQRT2;
        p.y = (fmaxf(fmaf(a.y, psc[c+1], psh[c+1]), 0.f) + fmaxf(fmaf(b.y, psc[c+1], psh[c+1]), 0.f)) * INV_SQRT2;
        p.z = (fmaxf(fmaf(a.z, psc[c+2], psh[c+2]), 0.f) + fmaxf(fmaf(b.z, psc[c+2], psh[c+2]), 0.f)) * INV_SQRT2;
        p.w = (fmaxf(fmaf(a.w, psc[c+3], psh[c+3]), 0.f) + fmaxf(fmaf(b.w, psc[c+3], psh[c+3]), 0.f)) * INV_SQRT2;
        out4[i] = p;
        atomicAdd(&es[c + 0], p.x);
        atomicAdd(&es[c + 1], p.y);
        atomicAdd(&es[c + 2], p.z);
        atomicAdd(&es[c + 3], p.w);
    }
    __syncthreads();
    if (tid < 128) {
        float v = es[tid];
        embraw[g * 128 + tid] = v;
        atomicAdd(&statsOut[tid], v);
        atomicAdd(&statsOut[128 + tid], v * v);
    }
}

// ---------------- embedding BN apply (inline coefs) ----------------
__global__ void eapply_kernel(const float* __restrict__ raw,
                              const float* __restrict__ bnG, const float* __restrict__ bnB,
                              const float* __restrict__ statsIn,
                              float* __restrict__ cat, int layer) {
    int idx = blockIdx.x * blockDim.x + threadIdx.x;
    if (idx < G_GRAPHS * H_DIM) {
        int g = idx >> 7, c = idx & 127;
        float sv = statsIn[c], qv = statsIn[128 + c];
        float m = sv / (float)G_GRAPHS, v = qv / (float)G_GRAPHS - m * m;
        float sc = bnG[c] * rsqrtf(v + BN_EPS);
        float sh = fmaf(-m, sc, bnB[c]);
        cat[g * (L_LAYERS * H_DIM) + layer * H_DIM + c] =
            fmaxf(fmaf(raw[idx], sc, sh), 0.f);
    }
}

// ---------------- final linear ----------------
__global__ void final_linear_kernel(const float* __restrict__ emb, const float* __restrict__ W,
                                    const float* __restrict__ b, float* __restrict__ out) {
    const int g = blockIdx.x, lane = threadIdx.x;
    float acc[C_CLASSES];
    #pragma unroll
    for (int c = 0; c < C_CLASSES; c++) acc[c] = 0.f;
    for (int k = lane; k < L_LAYERS * H_DIM; k += 32) {
        float e = emb[g * (L_LAYERS * H_DIM) + k];
        #pragma unroll
        for (int c = 0; c < C_CLASSES; c++)
            acc[c] = fmaf(e, W[k * C_CLASSES + c], acc[c]);
    }
    #pragma unroll
    for (int off = 16; off > 0; off >>= 1)
        #pragma unroll
        for (int c = 0; c < C_CLASSES; c++)
            acc[c] += __shfl_down_sync(0xFFFFFFFFu, acc[c], off);
    if (lane == 0) {
        #pragma unroll
        for (int c = 0; c < C_CLASSES; c++)
            out[g * C_CLASSES + c] = acc[c] + b[c];
    }
}

// ---------------- host orchestration ----------------
extern "C" void kernel_launch(void* const* d_in, const int* in_sizes, int n_in,
                              void* d_out, int out_size) {
    const float* x           = (const float*)d_in[0];
    const int*   ei          = (const int*)d_in[1];
    const int*   src         = ei;
    const int*   dst         = ei + E_EDGES;
    const float* lin_start_w = (const float*)d_in[2];
    const float* lin_start_b = (const float*)d_in[3];
    const float* bn_start_g  = (const float*)d_in[4];
    const float* bn_start_b  = (const float*)d_in[5];
    const float* conv_w1     = (const float*)d_in[6];
    const float* conv_b1     = (const float*)d_in[7];
    const float* conv_bn_g   = (const float*)d_in[8];
    const float* conv_bn_b   = (const float*)d_in[9];
    const float* conv_w2     = (const float*)d_in[10];
    const float* conv_b2     = (const float*)d_in[11];
    const float* bn_g        = (const float*)d_in[12];
    const float* bn_b        = (const float*)d_in[13];
    const float* bne_g       = (const float*)d_in[14];
    const float* bne_b       = (const float*)d_in[15];
    const float* lin_w       = (const float*)d_in[16];
    const float* lin_b       = (const float*)d_in[17];
    float* out = (float*)d_out;

    float *bufA, *bufB, *bufX, *embraw, *embcat, *statsAll;
    __nv_bfloat16* wimg;
    cudaGetSymbolAddress((void**)&bufA,     g_bufA);
    cudaGetSymbolAddress((void**)&bufB,     g_bufB);
    cudaGetSymbolAddress((void**)&bufX,     g_X);
    cudaGetSymbolAddress((void**)&embraw,   g_embraw);
    cudaGetSymbolAddress((void**)&embcat,   g_embcat);
    cudaGetSymbolAddress((void**)&statsAll, g_statsAll);
    cudaGetSymbolAddress((void**)&wimg,     g_wimg);

    cudaFuncSetAttribute(tc_gemm, cudaFuncAttributeMaxDynamicSharedMemorySize, TC_SMEM);
    cudaFuncSetAttribute(agg_mma, cudaFuncAttributeMaxDynamicSharedMemorySize, AG_SMEM);

    transw_kernel<<<8, 256>>>(lin_start_w, conv_w1, conv_w2, wimg, statsAll);

    float* slot0 = statsAll;

    // Stage 0: bufA = x @ W_start + b (fp32, stats slot0)
    tc_gemm<<<N_NODES / 128, 256, TC_SMEM>>>(
        x, wimg, lin_start_b, nullptr, nullptr, nullptr, 0.f, 0,
        bufA, nullptr, nullptr, 0, slot0);

    for (int i = 0; i < L_LAYERS; i++) {
        const int n = N_NODES >> i;
        const int npg = NPG0 >> i;
        float* slotH = statsAll + (1 + 3 * i) * 256;
        float* slotG = statsAll + (2 + 3 * i) * 256;
        float* slotE = statsAll + (3 + 3 * i) * 256;

        __nv_bfloat16* Yhi = (__nv_bfloat16*)bufB;
        __nv_bfloat16* Ylo = Yhi + (size_t)n * 128;

        // Y = op(x) @ W1  (bf16 hi/lo planes; layer0 fuses bn_start+relu)
        const float* ain = (i == 0) ? (const float*)bufA : (const float*)bufX;
        tc_gemm<<<n / 128, 256, TC_SMEM>>>(
            ain, wimg + (size_t)(1 + i) * 32768, nullptr,
            (i == 0) ? bn_start_g : nullptr, (i == 0) ? bn_start_b : nullptr,
            (i == 0) ? slot0 : nullptr, (float)N_NODES, (i == 0) ? 1 : 0,
            nullptr, Yhi, Ylo, 1, nullptr);

        // H = (I + A) Y + b1  (tensor MMA; stats slotH)
        agg_mma<<<n / 128, 256, AG_SMEM>>>(
            Yhi, Ylo, src, dst, conv_b1 + i * H_DIM, bufA, slotH, i);

        // G = relu(bn(H)) @ W2 + b2  (fp32; stats slotG)
        tc_gemm<<<n / 128, 256, TC_SMEM>>>(
            bufA, wimg + (size_t)(4 + i) * 32768, conv_b2 + i * H_DIM,
            conv_bn_g + i * H_DIM, conv_bn_b + i * H_DIM, slotH, (float)n, 1,
            bufB, nullptr, nullptr, 0, slotG);

        // pool: bn(G)+relu -> Haar -> x_{i+1}; embd sums + stats slotE
        pool_kernel<<<G_GRAPHS, 256>>>(
            bufB, bn_g + i * H_DIM, bn_b + i * H_DIM, slotG, (float)n,
            bufX, embraw, slotE, npg);

        eapply_kernel<<<(G_GRAPHS * H_DIM + 255) / 256, 256>>>(
            embraw, bne_g + i * H_DIM, bne_b + i * H_DIM, slotE, embcat, i);
    }

    final_linear_kernel<<<G_GRAPHS, 32>>>(embcat, lin_w, lin_b, out);
}

// round 7
// speedup vs baseline: 1.4844x; 1.1465x over previous
#include <cuda_runtime.h>
#include <cuda_bf16.h>
#include <math.h>
#include <stdint.h>

// ---------------- problem constants ----------------
#define N_NODES   131072
#define G_GRAPHS  1024
#define NPG0      128
#define H_DIM     128
#define E_EDGES   2097152
#define EPG       2048
#define L_LAYERS  3
#define C_CLASSES 10
#define BN_EPS    1e-5f
#define INV_SQRT2 0.70710678118654752440f
#define N_SLOTS   10

// ---------------- scratch ----------------
__device__ float g_bufA[(size_t)N_NODES * H_DIM];
__device__ float g_bufB[(size_t)N_NODES * H_DIM];
__device__ float g_X[(size_t)(N_NODES / 2) * H_DIM];
__device__ float g_embraw[L_LAYERS * G_GRAPHS * H_DIM];
__device__ float g_statsAll[N_SLOTS * 256];
__device__ __nv_bfloat16 g_wimg[7 * 2 * 16384];   // [7 weights][hi|lo][K=128][N=128]

// ---------------- helpers ----------------
__device__ __forceinline__ uint32_t smem_u32(const void* p) {
    uint32_t a;
    asm("{ .reg .u64 t; cvta.to.shared.u64 t, %1; cvt.u32.u64 %0, t; }" : "=r"(a) : "l"(p));
    return a;
}
__device__ __forceinline__ uint32_t pack2(__nv_bfloat16 a, __nv_bfloat16 b) {
    __nv_bfloat162 t; t.x = a; t.y = b; return *(uint32_t*)&t;
}
#define LDSM_X4(r, a) \
    asm volatile("ldmatrix.sync.aligned.m8n8.x4.shared.b16 {%0,%1,%2,%3}, [%4];" \
        : "=r"((r)[0]), "=r"((r)[1]), "=r"((r)[2]), "=r"((r)[3]) : "r"(a))
#define LDSM_X4T(r, a) \
    asm volatile("ldmatrix.sync.aligned.m8n8.x4.trans.shared.b16 {%0,%1,%2,%3}, [%4];" \
        : "=r"((r)[0]), "=r"((r)[1]), "=r"((r)[2]), "=r"((r)[3]) : "r"(a))
#define MMA_BF16(d, a, b0, b1) \
    asm volatile("mma.sync.aligned.m16n8k16.row.col.f32.bf16.bf16.f32 " \
        "{%0,%1,%2,%3}, {%4,%5,%6,%7}, {%8,%9}, {%0,%1,%2,%3};" \
        : "+f"((d)[0]), "+f"((d)[1]), "+f"((d)[2]), "+f"((d)[3]) \
        : "r"((a)[0]), "r"((a)[1]), "r"((a)[2]), "r"((a)[3]), "r"(b0), "r"(b1))

#define SK_BYTES  272   // full-K bf16 row stride (136 elems)
#define AH_BYTES  144   // half-K bf16 row stride (72 elems)

// ---- shared smem layout (both big kernels) ----
#define SB_HI     0        // full B plane hi (34816) — in fused: W1 hi, later Y hi
#define SB_LO     34816    // full B plane lo          — in fused: W1 lo, later Y lo
#define SA_HI     69632    // A half hi (18432) — in fused phase2: cnt/Abar (34816)
#define SA_LO     88064    // A half lo (18432)
#define SO_BIAS   106496
#define SO_SCALE  107008
#define SO_SHIFT  107520
#define BIG_SMEM  108032

// ---------------- weight bf16 split + stats zero ----------------
__global__ void transw_kernel(const float* __restrict__ w0, const float* __restrict__ w1,
                              const float* __restrict__ w2, __nv_bfloat16* __restrict__ img,
                              float* __restrict__ statsAll) {
    int b = blockIdx.x;
    if (b == 7) {
        for (int i = threadIdx.x; i < N_SLOTS * 256; i += blockDim.x) statsAll[i] = 0.f;
        return;
    }
    const float* W = (b == 0) ? w0 : ((b <= 3) ? w1 + (size_t)(b - 1) * 16384
                                               : w2 + (size_t)(b - 4) * 16384);
    __nv_bfloat16* hi = img + (size_t)b * 32768;
    __nv_bfloat16* lo = hi + 16384;
    for (int i = threadIdx.x; i < 16384; i += blockDim.x) {
        float v = W[i];
        __nv_bfloat16 h = __float2bfloat16(v);
        hi[i] = h;
        lo[i] = __float2bfloat16(v - __bfloat162float(h));
    }
}

// load A half-K (64 cols at kh*64) -> bf16 hi/lo split into SA planes
__device__ __forceinline__ void load_a_half(
    const char* smem, const float4* A4, int kh, int tid, int mode,
    const float* sscale, const float* sshift) {
    #pragma unroll
    for (int it = 0; it < 4; it++) {
        int i = tid + it * 256;            // 1024 groups of 8 floats
        int row = i >> 3, g = i & 7;
        float4 u = A4[row * 32 + kh * 16 + g * 2];
        float4 v = A4[row * 32 + kh * 16 + g * 2 + 1];
        float xv[8] = {u.x, u.y, u.z, u.w, v.x, v.y, v.z, v.w};
        if (mode) {
            int c0 = kh * 64 + g * 8;
            #pragma unroll
            for (int j = 0; j < 8; j++)
                xv[j] = fmaxf(fmaf(xv[j], sscale[c0 + j], sshift[c0 + j]), 0.f);
        }
        uint32_t hp[4], lp[4];
        #pragma unroll
        for (int j = 0; j < 4; j++) {
            __nv_bfloat16 h0 = __float2bfloat16(xv[2 * j]);
            __nv_bfloat16 h1 = __float2bfloat16(xv[2 * j + 1]);
            hp[j] = pack2(h0, h1);
            lp[j] = pack2(__float2bfloat16(xv[2 * j]     - __bfloat162float(h0)),
                          __float2bfloat16(xv[2 * j + 1] - __bfloat162float(h1)));
        }
        uint32_t off = (uint32_t)row * AH_BYTES + (uint32_t)g * 16;
        *(uint4*)(smem + SA_HI + off) = make_uint4(hp[0], hp[1], hp[2], hp[3]);
        *(uint4*)(smem + SA_LO + off) = make_uint4(lp[0], lp[1], lp[2], lp[3]);
    }
}

// 3-term MMA over one K half (local ks 0..3, global kidx = kh*4+ks)
__device__ __forceinline__ void mma_half(
    float acc[2][8][4], uint32_t sb, int kh, int wm, int wn, int lane) {
    const uint32_t aA = sb + SA_HI + (uint32_t)(wm * 32 + (lane & 15)) * AH_BYTES
                      + (uint32_t)(lane >> 4) * 16;
    const uint32_t aB = sb + SB_HI + (uint32_t)(lane & 15) * SK_BYTES
                      + (uint32_t)(wn * 128) + (uint32_t)(lane >> 4) * 16;
    #pragma unroll
    for (int ks = 0; ks < 4; ks++) {
        int kidx = kh * 4 + ks;
        uint32_t ah[2][4], al[2][4], bh[4][4], bl[4][4];
        #pragma unroll
        for (int mt = 0; mt < 2; mt++) {
            uint32_t ad = aA + (uint32_t)mt * (16 * AH_BYTES) + (uint32_t)ks * 32;
            LDSM_X4(ah[mt], ad);
            LDSM_X4(al[mt], ad + (SA_LO - SA_HI));
        }
        #pragma unroll
        for (int nt2 = 0; nt2 < 4; nt2++) {
            uint32_t bd = aB + (uint32_t)kidx * (16 * SK_BYTES) + (uint32_t)nt2 * 32;
            LDSM_X4T(bh[nt2], bd);
            LDSM_X4T(bl[nt2], bd + (SB_LO - SB_HI));
        }
        #pragma unroll
        for (int mt = 0; mt < 2; mt++)
            #pragma unroll
            for (int nt = 0; nt < 8; nt++) {
                uint32_t b0h = bh[nt >> 1][(nt & 1) * 2], b1h = bh[nt >> 1][(nt & 1) * 2 + 1];
                uint32_t b0l = bl[nt >> 1][(nt & 1) * 2], b1l = bl[nt >> 1][(nt & 1) * 2 + 1];
                MMA_BF16(acc[mt][nt], ah[mt], b0h, b1h);
                MMA_BF16(acc[mt][nt], ah[mt], b0l, b1l);
                MMA_BF16(acc[mt][nt], al[mt], b0h, b1h);
            }
    }
}

// epilogue: + bias, channel stats, fp32 store
__device__ __forceinline__ void epilogue_f32(
    float acc[2][8][4], const float* sbias, float* Cb, float* statsOut,
    int wm, int wn, int lane) {
    float s[8][2], q[8][2];
    #pragma unroll
    for (int nt = 0; nt < 8; nt++) { s[nt][0] = s[nt][1] = q[nt][0] = q[nt][1] = 0.f; }
    const int cbase = wn * 64 + (lane & 3) * 2;
    const int rbase = wm * 32 + (lane >> 2);
    #pragma unroll
    for (int mt = 0; mt < 2; mt++) {
        int r0 = rbase + mt * 16, r1 = r0 + 8;
        #pragma unroll
        for (int nt = 0; nt < 8; nt++) {
            int c = cbase + nt * 8;
            float b0 = sbias[c], b1 = sbias[c + 1];
            float y0 = acc[mt][nt][0] + b0, y1 = acc[mt][nt][1] + b1;
            float y2 = acc[mt][nt][2] + b0, y3 = acc[mt][nt][3] + b1;
            s[nt][0] += y0 + y2;           s[nt][1] += y1 + y3;
            q[nt][0] += y0 * y0 + y2 * y2; q[nt][1] += y1 * y1 + y3 * y3;
            *(float2*)(Cb + r0 * 128 + c) = make_float2(y0, y1);
            *(float2*)(Cb + r1 * 128 + c) = make_float2(y2, y3);
        }
    }
    #pragma unroll
    for (int off = 16; off >= 4; off >>= 1)
        #pragma unroll
        for (int nt = 0; nt < 8; nt++) {
            s[nt][0] += __shfl_down_sync(0xFFFFFFFFu, s[nt][0], off);
            s[nt][1] += __shfl_down_sync(0xFFFFFFFFu, s[nt][1], off);
            q[nt][0] += __shfl_down_sync(0xFFFFFFFFu, q[nt][0], off);
            q[nt][1] += __shfl_down_sync(0xFFFFFFFFu, q[nt][1], off);
        }
    if (lane < 4) {
        #pragma unroll
        for (int nt = 0; nt < 8; nt++) {
            int c = cbase + nt * 8;
            atomicAdd(&statsOut[c],           s[nt][0]);
            atomicAdd(&statsOut[c + 1],       s[nt][1]);
            atomicAdd(&statsOut[128 + c],     q[nt][0]);
            atomicAdd(&statsOut[128 + c + 1], q[nt][1]);
        }
    }
}

// ---------------- tc_gemm: C = op(A) @ W + bias, + stats (K-split, 2 CTA/SM) ---
__global__ __launch_bounds__(256, 2) void tc_gemm(
    const float* __restrict__ A, const __nv_bfloat16* __restrict__ Wimg,
    const float* __restrict__ bias,
    const float* __restrict__ bnG, const float* __restrict__ bnB,
    const float* __restrict__ statsIn, float nIn, int mode,
    float* __restrict__ Cf, float* __restrict__ statsOut) {
    extern __shared__ char smem[];
    const uint32_t sb = smem_u32(smem);
    const int tid = threadIdx.x, wid = tid >> 5, lane = tid & 31;
    const int wm = wid >> 1, wn = wid & 1;

    float* sbias  = (float*)(smem + SO_BIAS);
    float* sscale = (float*)(smem + SO_SCALE);
    float* sshift = (float*)(smem + SO_SHIFT);
    if (tid < 128) {
        sbias[tid] = bias[tid];
        if (mode) {
            float s = statsIn[tid], q = statsIn[128 + tid];
            float m = s / nIn, v = q / nIn - m * m;
            float sc = bnG[tid] * rsqrtf(v + BN_EPS);
            sscale[tid] = sc;
            sshift[tid] = fmaf(-m, sc, bnB[tid]);
        }
    }
    __syncthreads();   // coefs visible to ALL threads before any A load

    // full B planes
    {
        const uint4* bh = (const uint4*)Wimg;
        #pragma unroll
        for (int it = 0; it < 8; it++) {
            int i = tid + it * 256;
            int k = i >> 4, g = i & 15;
            uint32_t off = (uint32_t)k * SK_BYTES + (uint32_t)g * 16;
            *(uint4*)(smem + SB_HI + off) = bh[i];
            *(uint4*)(smem + SB_LO + off) = bh[2048 + i];
        }
    }
    const float4* A4 = (const float4*)(A + (size_t)blockIdx.x * 128 * 128);

    float acc[2][8][4];
    #pragma unroll
    for (int mt = 0; mt < 2; mt++)
        #pragma unroll
        for (int nt = 0; nt < 8; nt++)
            #pragma unroll
            for (int j = 0; j < 4; j++) acc[mt][nt][j] = 0.f;

    load_a_half(smem, A4, 0, tid, mode, sscale, sshift);
    __syncthreads();
    mma_half(acc, sb, 0, wm, wn, lane);
    __syncthreads();
    load_a_half(smem, A4, 1, tid, mode, sscale, sshift);
    __syncthreads();
    mma_half(acc, sb, 1, wm, wn, lane);

    epilogue_f32(acc, sbias, Cf + (size_t)blockIdx.x * 128 * 128, statsOut, wm, wn, lane);
}

// ---------------- fused layer: H = (I+A) * (op(x) @ W1) + b1, + stats ----------
__global__ __launch_bounds__(256, 2) void fused_layer(
    const float* __restrict__ A, const __nv_bfloat16* __restrict__ W1img,
    const int* __restrict__ src, const int* __restrict__ dst,
    const float* __restrict__ bias,
    const float* __restrict__ bnG, const float* __restrict__ bnB,
    const float* __restrict__ statsIn, float nIn, int mode,
    float* __restrict__ H, float* __restrict__ statsOut, int layer) {
    extern __shared__ char smem[];
    const uint32_t sb = smem_u32(smem);
    const int tid = threadIdx.x, wid = tid >> 5, lane = tid & 31;
    const int wm = wid >> 1, wn = wid & 1;

    float* sbias  = (float*)(smem + SO_BIAS);
    float* sscale = (float*)(smem + SO_SCALE);
    float* sshift = (float*)(smem + SO_SHIFT);
    if (tid < 128) {
        sbias[tid] = bias[tid];
        if (mode) {
            float s = statsIn[tid], q = statsIn[128 + tid];
            float m = s / nIn, v = q / nIn - m * m;
            float sc = bnG[tid] * rsqrtf(v + BN_EPS);
            sscale[tid] = sc;
            sshift[tid] = fmaf(-m, sc, bnB[tid]);
        }
    }
    __syncthreads();   // coefs visible to ALL threads before any A load

    // W1 full planes
    {
        const uint4* bh = (const uint4*)W1img;
        #pragma unroll
        for (int it = 0; it < 8; it++) {
            int i = tid + it * 256;
            int k = i >> 4, g = i & 15;
            uint32_t off = (uint32_t)k * SK_BYTES + (uint32_t)g * 16;
            *(uint4*)(smem + SB_HI + off) = bh[i];
            *(uint4*)(smem + SB_LO + off) = bh[2048 + i];
        }
    }
    const float4* A4 = (const float4*)(A + (size_t)blockIdx.x * 128 * 128);

    float acc[2][8][4];
    #pragma unroll
    for (int mt = 0; mt < 2; mt++)
        #pragma unroll
        for (int nt = 0; nt < 8; nt++)
            #pragma unroll
            for (int j = 0; j < 4; j++) acc[mt][nt][j] = 0.f;

    load_a_half(smem, A4, 0, tid, mode, sscale, sshift);
    __syncthreads();
    mma_half(acc, sb, 0, wm, wn, lane);
    __syncthreads();
    load_a_half(smem, A4, 1, tid, mode, sscale, sshift);
    __syncthreads();
    mma_half(acc, sb, 1, wm, wn, lane);
    __syncthreads();   // all warps done reading W1 + A planes

    // Y fragments -> bf16 hi/lo planes (overwrite W1 planes); zero cnt region
    {
        const int cbase = wn * 64 + (lane & 3) * 2;
        const int rbase = wm * 32 + (lane >> 2);
        #pragma unroll
        for (int mt = 0; mt < 2; mt++) {
            int r0 = rbase + mt * 16, r1 = r0 + 8;
            #pragma unroll
            for (int nt = 0; nt < 8; nt++) {
                int c = cbase + nt * 8;
                float y0 = acc[mt][nt][0], y1 = acc[mt][nt][1];
                float y2 = acc[mt][nt][2], y3 = acc[mt][nt][3];
                __nv_bfloat16 h0 = __float2bfloat16(y0), h1 = __float2bfloat16(y1);
                __nv_bfloat16 h2 = __float2bfloat16(y2), h3 = __float2bfloat16(y3);
                *(uint32_t*)(smem + SB_HI + (uint32_t)r0 * SK_BYTES + (uint32_t)c * 2) = pack2(h0, h1);
                *(uint32_t*)(smem + SB_HI + (uint32_t)r1 * SK_BYTES + (uint32_t)c * 2) = pack2(h2, h3);
                *(uint32_t*)(smem + SB_LO + (uint32_t)r0 * SK_BYTES + (uint32_t)c * 2) =
                    pack2(__float2bfloat16(y0 - __bfloat162float(h0)),
                          __float2bfloat16(y1 - __bfloat162float(h1)));
                *(uint32_t*)(smem + SB_LO + (uint32_t)r1 * SK_BYTES + (uint32_t)c * 2) =
                    pack2(__float2bfloat16(y2 - __bfloat162float(h2)),
                          __float2bfloat16(y3 - __bfloat162float(h3)));
            }
        }
        uint4* az = (uint4*)(smem + SA_HI);    // cnt/Abar: 34816 B = 2176 uint4
        for (int i = tid; i < 2176; i += 256) az[i] = make_uint4(0, 0, 0, 0);
    }
    __syncthreads();

    // build packed 16-bit pair counts via int atomics (proven path)
    // word layout per row: 68 uint32 (272 B); cols occupy words 0..63
    {
        int* cntw = (int*)(smem + SA_HI);
        const int gb = 1 << layer, npg = NPG0 >> layer;
        const int g0 = blockIdx.x * gb;
        const int tot = gb * EPG;
        for (int idx = tid; idx < tot; idx += 256) {
            int j = idx >> 11;
            int e = (g0 + j) * EPG + (idx & 2047);
            int nb = (g0 + j) * NPG0;
            int d = (dst[e] - nb) >> layer;
            int s = (src[e] - nb) >> layer;
            int row = j * npg + d, col = j * npg + s;
            atomicAdd(&cntw[row * 68 + (col >> 1)], 1 << ((col & 1) * 16));
        }
    }
    __syncthreads();

    // in-place convert counts -> bf16 Abar (+I); each thread owns its words
    {
        uint32_t* cw = (uint32_t*)(smem + SA_HI);
        for (int i = tid; i < 128 * 64; i += 256) {
            int row = i >> 6, w = i & 63;
            int col = w * 2;
            uint32_t v = cw[row * 68 + w];
            float v0 = (float)(v & 0xFFFFu) + ((row == col)     ? 1.f : 0.f);
            float v1 = (float)(v >> 16)     + ((row == col + 1) ? 1.f : 0.f);
            cw[row * 68 + w] = pack2(__float2bfloat16(v0), __float2bfloat16(v1));
        }
    }
    __syncthreads();

    // agg MMA: acc2 = Abar @ (Yhi + Ylo)
    float acc2[2][8][4];
    #pragma unroll
    for (int mt = 0; mt < 2; mt++)
        #pragma unroll
        for (int nt = 0; nt < 8; nt++)
            #pragma unroll
            for (int j = 0; j < 4; j++) acc2[mt][nt][j] = 0.f;
    {
        const uint32_t aA = sb + SA_HI + (uint32_t)(wm * 32 + (lane & 15)) * SK_BYTES
                          + (uint32_t)(lane >> 4) * 16;
        const uint32_t aB = sb + SB_HI + (uint32_t)(lane & 15) * SK_BYTES
                          + (uint32_t)(wn * 128) + (uint32_t)(lane >> 4) * 16;
        #pragma unroll
        for (int ks = 0; ks < 8; ks++) {
            uint32_t a[2][4], bh[4][4], bl[4][4];
            #pragma unroll
            for (int mt = 0; mt < 2; mt++)
                LDSM_X4(a[mt], aA + (uint32_t)mt * (16 * SK_BYTES) + (uint32_t)ks * 32);
            #pragma unroll
            for (int nt2 = 0; nt2 < 4; nt2++) {
                uint32_t bd = aB + (uint32_t)ks * (16 * SK_BYTES) + (uint32_t)nt2 * 32;
                LDSM_X4T(bh[nt2], bd);
                LDSM_X4T(bl[nt2], bd + (SB_LO - SB_HI));
            }
            #pragma unroll
            for (int mt = 0; mt < 2; mt++)
                #pragma unroll
                for (int nt = 0; nt < 8; nt++) {
                    uint32_t b0h = bh[nt >> 1][(nt & 1) * 2], b1h = bh[nt >> 1][(nt & 1) * 2 + 1];
                    uint32_t b0l = bl[nt >> 1][(nt & 1) * 2], b1l = bl[nt >> 1][(nt & 1) * 2 + 1];
                    MMA_BF16(acc2[mt][nt], a[mt], b0h, b1h);
                    MMA_BF16(acc2[mt][nt], a[mt], b0l, b1l);
                }
        }
    }
    epilogue_f32(acc2, sbias, H + (size_t)blockIdx.x * 128 * 128, statsOut, wm, wn, lane);
}

// ---------------- pool: inline BN+relu -> Haar -> graph sum + embd stats -------
__global__ __launch_bounds__(256) void pool_kernel(
    const float* __restrict__ Hin,
    const float* __restrict__ bnG, const float* __restrict__ bnB,
    const float* __restrict__ statsIn, float nIn,
    float* __restrict__ Xout, float* __restrict__ embraw,
    float* __restrict__ statsOut, int npg_in) {
    __shared__ float es[128], psc[128], psh[128];
    const int g = blockIdx.x, tid = threadIdx.x;
    if (tid < 128) {
        es[tid] = 0.f;
        float sv = statsIn[tid], qv = statsIn[128 + tid];
        float m = sv / nIn, v = qv / nIn - m * m;
        float c_ = bnG[tid] * rsqrtf(v + BN_EPS);
        psc[tid] = c_;
        psh[tid] = fmaf(-m, c_, bnB[tid]);
    }
    __syncthreads();

    const int npg_out = npg_in >> 1;
    const float4* in4 = (const float4*)(Hin + (size_t)g * npg_in * 128);
    float4* out4 = (float4*)(Xout + (size_t)g * npg_out * 128);

    for (int i = tid; i < npg_out * 32; i += 256) {
        int row = i >> 5, c4 = i & 31, c = c4 * 4;
        float4 a = in4[(2 * row) * 32 + c4];
        float4 b = in4[(2 * row + 1) * 32 + c4];
        float4 p;
        p.x = (fmaxf(fmaf(a.x, psc[c+0], psh[c+0]), 0.f) + fmaxf(fmaf(b.x, psc[c+0], psh[c+0]), 0.f)) * INV_SQRT2;
        p.y = (fmaxf(fmaf(a.y, psc[c+1], psh[c+1]), 0.f) + fmaxf(fmaf(b.y, psc[c+1], psh[c+1]), 0.f)) * INV_SQRT2;
        p.z = (fmaxf(fmaf(a.z, psc[c+2], psh[c+2]), 0.f) + fmaxf(fmaf(b.z, psc[c+2], psh[c+2]), 0.f)) * INV_SQRT2;
        p.w = (fmaxf(fmaf(a.w, psc[c+3], psh[c+3]), 0.f) + fmaxf(fmaf(b.w, psc[c+3], psh[c+3]), 0.f)) * INV_SQRT2;
        out4[i] = p;
        atomicAdd(&es[c + 0], p.x);
        atomicAdd(&es[c + 1], p.y);
        atomicAdd(&es[c + 2], p.z);
        atomicAdd(&es[c + 3], p.w);
    }
    __syncthreads();
    if (tid < 128) {
        float v = es[tid];
        embraw[g * 128 + tid] = v;
        atomicAdd(&statsOut[tid], v);
        atomicAdd(&statsOut[128 + tid], v * v);
    }
}

// ---------------- final linear with inline embedding-BN ------------------------
__global__ void final_linear_kernel(
    const float* __restrict__ embraw, const float* __restrict__ statsAll,
    const float* __restrict__ bneG, const float* __restrict__ bneB,
    const float* __restrict__ W, const float* __restrict__ b, float* __restrict__ out) {
    const int g = blockIdx.x, lane = threadIdx.x;
    float acc[C_CLASSES];
    #pragma unroll
    for (int c = 0; c < C_CLASSES; c++) acc[c] = 0.f;
    for (int k = lane; k < L_LAYERS * H_DIM; k += 32) {
        int layer = k >> 7, c = k & 127;
        const float* st = statsAll + (3 + 3 * layer) * 256;
        float m = st[c] / (float)G_GRAPHS;
        float v = st[128 + c] / (float)G_GRAPHS - m * m;
        float sc = bneG[layer * 128 + c] * rsqrtf(v + BN_EPS);
        float sh = fmaf(-m, sc, bneB[layer * 128 + c]);
        float e = fmaxf(fmaf(embraw[(size_t)layer * G_GRAPHS * 128 + g * 128 + c], sc, sh), 0.f);
        #pragma unroll
        for (int c10 = 0; c10 < C_CLASSES; c10++)
            acc[c10] = fmaf(e, W[k * C_CLASSES + c10], acc[c10]);
    }
    #pragma unroll
    for (int off = 16; off > 0; off >>= 1)
        #pragma unroll
        for (int c = 0; c < C_CLASSES; c++)
            acc[c] += __shfl_down_sync(0xFFFFFFFFu, acc[c], off);
    if (lane == 0) {
        #pragma unroll
        for (int c = 0; c < C_CLASSES; c++)
            out[g * C_CLASSES + c] = acc[c] + b[c];
    }
}

// ---------------- host orchestration ----------------
extern "C" void kernel_launch(void* const* d_in, const int* in_sizes, int n_in,
                              void* d_out, int out_size) {
    const float* x           = (const float*)d_in[0];
    const int*   ei          = (const int*)d_in[1];
    const int*   src         = ei;
    const int*   dst         = ei + E_EDGES;
    const float* lin_start_w = (const float*)d_in[2];
    const float* lin_start_b = (const float*)d_in[3];
    const float* bn_start_g  = (const float*)d_in[4];
    const float* bn_start_b  = (const float*)d_in[5];
    const float* conv_w1     = (const float*)d_in[6];
    const float* conv_b1     = (const float*)d_in[7];
    const float* conv_bn_g   = (const float*)d_in[8];
    const float* conv_bn_b   = (const float*)d_in[9];
    const float* conv_w2     = (const float*)d_in[10];
    const float* conv_b2     = (const float*)d_in[11];
    const float* bn_g        = (const float*)d_in[12];
    const float* bn_b        = (const float*)d_in[13];
    const float* bne_g       = (const float*)d_in[14];
    const float* bne_b       = (const float*)d_in[15];
    const float* lin_w       = (const float*)d_in[16];
    const float* lin_b       = (const float*)d_in[17];
    float* out = (float*)d_out;

    float *bufA, *bufB, *bufX, *embraw, *statsAll;
    __nv_bfloat16* wimg;
    cudaGetSymbolAddress((void**)&bufA,     g_bufA);
    cudaGetSymbolAddress((void**)&bufB,     g_bufB);
    cudaGetSymbolAddress((void**)&bufX,     g_X);
    cudaGetSymbolAddress((void**)&embraw,   g_embraw);
    cudaGetSymbolAddress((void**)&statsAll, g_statsAll);
    cudaGetSymbolAddress((void**)&wimg,     g_wimg);

    cudaFuncSetAttribute(tc_gemm, cudaFuncAttributeMaxDynamicSharedMemorySize, BIG_SMEM);
    cudaFuncSetAttribute(fused_layer, cudaFuncAttributeMaxDynamicSharedMemorySize, BIG_SMEM);

    transw_kernel<<<8, 256>>>(lin_start_w, conv_w1, conv_w2, wimg, statsAll);

    float* slot0 = statsAll;

    // Stage 0: bufA = x @ W_start + b  (stats slot0)
    tc_gemm<<<N_NODES / 128, 256, BIG_SMEM>>>(
        x, wimg, lin_start_b, nullptr, nullptr, nullptr, 0.f, 0, bufA, slot0);

    for (int i = 0; i < L_LAYERS; i++) {
        const int n = N_NODES >> i;
        const int npg = NPG0 >> i;
        float* slotH = statsAll + (1 + 3 * i) * 256;
        float* slotG = statsAll + (2 + 3 * i) * 256;
        float* slotE = statsAll + (3 + 3 * i) * 256;

        // fused: H = (I+A)(op(x)@W1) + b1   (layer0: op = BN(slot0)+relu, in-place bufA)
        const float* ain = (i == 0) ? (const float*)bufA : (const float*)bufX;
        fused_layer<<<n / 128, 256, BIG_SMEM>>>(
            ain, wimg + (size_t)(1 + i) * 32768, src, dst, conv_b1 + i * H_DIM,
            (i == 0) ? bn_start_g : nullptr, (i == 0) ? bn_start_b : nullptr,
            (i == 0) ? slot0 : nullptr, (float)N_NODES, (i == 0) ? 1 : 0,
            bufA, slotH, i);

        // G = relu(bn(H)) @ W2 + b2   (stats slotG)
        tc_gemm<<<n / 128, 256, BIG_SMEM>>>(
            bufA, wimg + (size_t)(4 + i) * 32768, conv_b2 + i * H_DIM,
            conv_bn_g + i * H_DIM, conv_bn_b + i * H_DIM, slotH, (float)n, 1,
            bufB, slotG);

        // pool: bn(G)+relu -> Haar -> x_{i+1}; embd sums + stats slotE
        pool_kernel<<<G_GRAPHS, 256>>>(
            bufB, bn_g + i * H_DIM, bn_b + i * H_DIM, slotG, (float)n,
            bufX, embraw + (size_t)i * G_GRAPHS * H_DIM, slotE, npg);
    }

    final_linear_kernel<<<G_GRAPHS, 32>>>(
        embraw, statsAll, bne_g, bne_b, lin_w, lin_b, out);
}